// round 10
// baseline (speedup 1.0000x reference)
#include <cuda_runtime.h>
#include <cuda_bf16.h>
#include <cstdint>

#define D   4096
#define BSR 4096
#define SEQ 1024
#define NH  32
#define HD  128
#define LR  16
#define SCALE 0.08838834764831845f

// ------------------------- device scratch ---------------------------------
__device__ __nv_bfloat16 g_xh[(size_t)BSR * D], g_xl[(size_t)BSR * D];
__device__ __nv_bfloat16 g_Wqh[(size_t)D * D], g_Wql[(size_t)D * D];
__device__ __nv_bfloat16 g_Wkh[(size_t)D * D], g_Wkl[(size_t)D * D];
__device__ __nv_bfloat16 g_Wvh[(size_t)D * D], g_Wvl[(size_t)D * D];
__device__ __nv_bfloat16 g_Woh[(size_t)D * D], g_Wol[(size_t)D * D];
__device__ __nv_bfloat16 g_Qh[(size_t)BSR * D], g_Ql[(size_t)BSR * D];
__device__ __nv_bfloat16 g_Kh[(size_t)BSR * D], g_Kl[(size_t)BSR * D];
__device__ __nv_bfloat16 g_Vh[(size_t)BSR * D], g_Vl[(size_t)BSR * D];
__device__ __nv_bfloat16 g_Oh[(size_t)BSR * D], g_Ol[(size_t)BSR * D];

// ------------------------- PTX helpers (base-target only) ------------------
__device__ __forceinline__ uint32_t smem_to_u32(const void* p) {
    uint32_t a;
    asm("{ .reg .u64 t; cvta.to.shared.u64 t, %1; cvt.u32.u64 %0, t; }"
        : "=r"(a) : "l"(p));
    return a;
}
#define CP16(dst, src) \
    asm volatile("cp.async.cg.shared.global [%0], [%1], 16;" \
                 :: "r"(dst), "l"(src))
#define CP_COMMIT() asm volatile("cp.async.commit_group;" ::: "memory")
#define CP_WAIT1()  asm volatile("cp.async.wait_group 1;" ::: "memory")
#define CP_WAIT0()  asm volatile("cp.async.wait_group 0;" ::: "memory")

#define LDSM4(r0, r1, r2, r3, addr) \
    asm volatile("ldmatrix.sync.aligned.m8n8.x4.shared.b16 {%0,%1,%2,%3}, [%4];" \
                 : "=r"(r0), "=r"(r1), "=r"(r2), "=r"(r3) : "r"(addr))
#define LDSM4T(r0, r1, r2, r3, addr) \
    asm volatile("ldmatrix.sync.aligned.m8n8.x4.trans.shared.b16 {%0,%1,%2,%3}, [%4];" \
                 : "=r"(r0), "=r"(r1), "=r"(r2), "=r"(r3) : "r"(addr))
#define LDSM2(r0, r1, addr) \
    asm volatile("ldmatrix.sync.aligned.m8n8.x2.shared.b16 {%0,%1}, [%2];" \
                 : "=r"(r0), "=r"(r1) : "r"(addr))
#define MMA16816(c, a0, a1, a2, a3, b0, b1) \
    asm volatile("mma.sync.aligned.m16n8k16.row.col.f32.bf16.bf16.f32 " \
                 "{%0,%1,%2,%3}, {%4,%5,%6,%7}, {%8,%9}, {%0,%1,%2,%3};" \
                 : "+f"((c)[0]), "+f"((c)[1]), "+f"((c)[2]), "+f"((c)[3]) \
                 : "r"(a0), "r"(a1), "r"(a2), "r"(a3), "r"(b0), "r"(b1))

// ------------------------- split / merge kernels --------------------------
__global__ void split8(const float* __restrict__ in,
                       __nv_bfloat16* __restrict__ hi,
                       __nv_bfloat16* __restrict__ lo) {
    size_t i = ((size_t)blockIdx.x * 256 + threadIdx.x) * 8;
    float v[8];
    *(float4*)&v[0] = *(const float4*)(in + i);
    *(float4*)&v[4] = *(const float4*)(in + i + 4);
    __nv_bfloat16 h[8], l[8];
#pragma unroll
    for (int j = 0; j < 8; j++) {
        h[j] = __float2bfloat16(v[j]);
        l[j] = __float2bfloat16(v[j] - __bfloat162float(h[j]));
    }
    *(float4*)(hi + i) = *(float4*)h;
    *(float4*)(lo + i) = *(float4*)l;
}

__global__ void merge_split(const float* __restrict__ w,
                            const float* __restrict__ a,
                            const float* __restrict__ b,
                            __nv_bfloat16* __restrict__ hi,
                            __nv_bfloat16* __restrict__ lo) {
    int idx = blockIdx.x * 256 + threadIdx.x;
    int n = idx >> 12, k = idx & (D - 1);
    float acc = w[idx];
#pragma unroll
    for (int r = 0; r < LR; r++)
        acc += 2.0f * __ldg(&b[n * LR + r]) * __ldg(&a[r * D + k]);
    __nv_bfloat16 h = __float2bfloat16(acc);
    hi[idx] = h;
    lo[idx] = __float2bfloat16(acc - __bfloat162float(h));
}

// ------------- bf16-split GEMM (NT) on mma.sync tensor cores --------------
// C = Ah*Bh^T + Ah*Bl^T + Al*Bh^T.  BM=BN=128, BK=64, 256 thr (8 warps 2x4).
// 3-stage cp.async pipeline, single barrier per chunk, tail-drained.
// MMAs are PASS-MAJOR: all hh, then all hl, then all lh — no back-to-back
// RAW chains on one accumulator (reuse distance 16). Per-acc addition order
// (hh -> hl -> lh) is preserved, so results are bitwise identical to R9.
// MODE: 0 = fp32 store (final out), 1 = bf16 hi/lo split store (V),
//       2 = RoPE + split (K),       3 = RoPE + scale + split (Q).
#define GTILE   16384
#define GSTAGE  (4 * GTILE)
#define NSTAGE  3
#define GEMM_SMEM (NSTAGE * GSTAGE)
#define NCHUNK  64   // D / BK

template <int MODE>
__global__ void __launch_bounds__(256, 1) gemm_mma3(
    const __nv_bfloat16* __restrict__ Ah, const __nv_bfloat16* __restrict__ Al,
    const __nv_bfloat16* __restrict__ Bh, const __nv_bfloat16* __restrict__ Bl,
    float* __restrict__ C,
    __nv_bfloat16* __restrict__ Ch, __nv_bfloat16* __restrict__ Cl,
    const float* __restrict__ fc, const float* __restrict__ fs) {
    extern __shared__ char smch[];
    const uint32_t smb = smem_to_u32(smch);
    const int tid = threadIdx.x, lane = tid & 31, wid = tid >> 5;
    const int warp_m = wid & 1;
    const int warp_n = wid >> 1;
    const int bm = blockIdx.y * 128, bn = blockIdx.x * 128;

    float acc[4][4][4];
#pragma unroll
    for (int i = 0; i < 4; i++)
#pragma unroll
        for (int j = 0; j < 4; j++)
#pragma unroll
            for (int k = 0; k < 4; k++) acc[i][j][k] = 0.0f;

    const int r0 = tid >> 3, c0 = tid & 7;
    const uint32_t dst0 = r0 * 128 + (uint32_t)((c0 ^ (r0 & 7)) * 16);
    const __nv_bfloat16* gAh = Ah + ((size_t)(bm + r0) << 12) + c0 * 8;
    const __nv_bfloat16* gAl = Al + ((size_t)(bm + r0) << 12) + c0 * 8;
    const __nv_bfloat16* gBh = Bh + ((size_t)(bn + r0) << 12) + c0 * 8;
    const __nv_bfloat16* gBl = Bl + ((size_t)(bn + r0) << 12) + c0 * 8;

#define ISSUE(ck, st) do {                                                     \
        const uint32_t sb_ = smb + (st) * GSTAGE + dst0;                       \
        const size_t go_ = (size_t)(ck) * 64;                                  \
        _Pragma("unroll")                                                      \
        for (int j = 0; j < 4; j++) {                                          \
            const uint32_t d_ = sb_ + j * 32 * 128;                            \
            const size_t s_ = go_ + ((size_t)j << 17);                         \
            CP16(d_,             (const char*)(gAh + s_));                     \
            CP16(d_ + GTILE,     (const char*)(gAl + s_));                     \
            CP16(d_ + 2 * GTILE, (const char*)(gBh + s_));                     \
            CP16(d_ + 3 * GTILE, (const char*)(gBl + s_));                     \
        }                                                                      \
        CP_COMMIT();                                                           \
    } while (0)

    ISSUE(0, 0);
    ISSUE(1, 1);

    const int arow = warp_m * 64 + (lane & 15);
    const int akh  = lane >> 4;
    const int brow = warp_n * 32 + (lane & 7);
    const int bkh  = (lane >> 3) & 1;

    for (int ck = 0; ck < NCHUNK; ck++) {
        const int st = ck % NSTAGE;
        if (ck + 2 >= NCHUNK) { CP_WAIT0(); } else { CP_WAIT1(); }
        __syncthreads();
        if (ck + 2 < NCHUNK) ISSUE(ck + 2, (ck + 2) % NSTAGE);

        const uint32_t sAh = smb + st * GSTAGE;
        const uint32_t sAl = sAh + GTILE;
        const uint32_t sBh = sAh + 2 * GTILE;
        const uint32_t sBl = sAh + 3 * GTILE;

#pragma unroll
        for (int ks = 0; ks < 4; ks++) {
            uint32_t ah[4][4], al[4][4], bh[4][2], bl[4][2];
#pragma unroll
            for (int mt = 0; mt < 4; mt++) {
                const int r = arow + mt * 16;
                const uint32_t adr = r * 128 + (((ks * 2 + akh) ^ (r & 7)) * 16);
                LDSM4(ah[mt][0], ah[mt][1], ah[mt][2], ah[mt][3], sAh + adr);
                LDSM4(al[mt][0], al[mt][1], al[mt][2], al[mt][3], sAl + adr);
            }
#pragma unroll
            for (int nt = 0; nt < 4; nt++) {
                const int r = brow + nt * 8;
                const uint32_t adr = r * 128 + (((ks * 2 + bkh) ^ (r & 7)) * 16);
                LDSM2(bh[nt][0], bh[nt][1], sBh + adr);
                LDSM2(bl[nt][0], bl[nt][1], sBl + adr);
            }
            // ---- pass-major MMA issue (chain distance 16) ----
#pragma unroll
            for (int mt = 0; mt < 4; mt++)
#pragma unroll
                for (int nt = 0; nt < 4; nt++)
                    MMA16816(acc[mt][nt], ah[mt][0], ah[mt][1], ah[mt][2], ah[mt][3],
                             bh[nt][0], bh[nt][1]);
#pragma unroll
            for (int mt = 0; mt < 4; mt++)
#pragma unroll
                for (int nt = 0; nt < 4; nt++)
                    MMA16816(acc[mt][nt], ah[mt][0], ah[mt][1], ah[mt][2], ah[mt][3],
                             bl[nt][0], bl[nt][1]);
#pragma unroll
            for (int mt = 0; mt < 4; mt++)
#pragma unroll
                for (int nt = 0; nt < 4; nt++)
                    MMA16816(acc[mt][nt], al[mt][0], al[mt][1], al[mt][2], al[mt][3],
                             bh[nt][0], bh[nt][1]);
        }
    }

    // epilogue
#pragma unroll
    for (int mt = 0; mt < 4; mt++) {
        const int row = bm + warp_m * 64 + mt * 16 + (lane >> 2);
#pragma unroll
        for (int nt = 0; nt < 4; nt++) {
            const int col = bn + warp_n * 32 + nt * 8 + (lane & 3) * 2;
            float v0 = acc[mt][nt][0], v1 = acc[mt][nt][1];
            float v2 = acc[mt][nt][2], v3 = acc[mt][nt][3];
            if (MODE >= 2) {
                const int i = (col & (HD - 1)) >> 1;
                const int s1 = row & (SEQ - 1);
                const int s2 = (row + 8) & (SEQ - 1);
                const float c1 = __ldg(&fc[s1 * 64 + i]), n1 = __ldg(&fs[s1 * 64 + i]);
                const float c2 = __ldg(&fc[s2 * 64 + i]), n2 = __ldg(&fs[s2 * 64 + i]);
                float t;
                t  = v0 * c1 - v1 * n1; v1 = v0 * n1 + v1 * c1; v0 = t;
                t  = v2 * c2 - v3 * n2; v3 = v2 * n2 + v3 * c2; v2 = t;
            }
            if (MODE == 3) { v0 *= SCALE; v1 *= SCALE; v2 *= SCALE; v3 *= SCALE; }
            if (MODE == 0) {
                *(float2*)&C[(size_t)row * D + col]       = make_float2(v0, v1);
                *(float2*)&C[(size_t)(row + 8) * D + col] = make_float2(v2, v3);
            } else {
                __nv_bfloat16 h0 = __float2bfloat16(v0), h1 = __float2bfloat16(v1);
                __nv_bfloat162 hp; hp.x = h0; hp.y = h1;
                *(__nv_bfloat162*)&Ch[(size_t)row * D + col] = hp;
                __nv_bfloat162 lp;
                lp.x = __float2bfloat16(v0 - __bfloat162float(h0));
                lp.y = __float2bfloat16(v1 - __bfloat162float(h1));
                *(__nv_bfloat162*)&Cl[(size_t)row * D + col] = lp;
                __nv_bfloat16 h2 = __float2bfloat16(v2), h3 = __float2bfloat16(v3);
                __nv_bfloat162 hq; hq.x = h2; hq.y = h3;
                *(__nv_bfloat162*)&Ch[(size_t)(row + 8) * D + col] = hq;
                __nv_bfloat162 lq;
                lq.x = __float2bfloat16(v2 - __bfloat162float(h2));
                lq.y = __float2bfloat16(v3 - __bfloat162float(h3));
                *(__nv_bfloat162*)&Cl[(size_t)(row + 8) * D + col] = lq;
            }
        }
    }
}

// ---------------- MMA flash attention (bf16 hi/lo 3-term, causal) ----------
// Same structure as R9; MMA issue reordered pass-major (per-acc order kept).
#define AT_Q    0
#define AT_QL   32768
#define AT_ST   65536
#define AT_STSZ 65536   // Kh | Kl | Vh | Vl (16KB each)
#define ATTN_SMEM (AT_ST + 2 * AT_STSZ)

__global__ void __launch_bounds__(256, 1) attn_mma() {
    extern __shared__ char smc[];
    const uint32_t smb = smem_to_u32(smc);
    const int b = blockIdx.z, h = blockIdx.y, qt = blockIdx.x;
    const int q0 = qt * 128;
    const int tid = threadIdx.x, lane = tid & 31, wid = tid >> 5;

    const size_t qoff = ((size_t)(b * SEQ + q0) << 12) + (size_t)h * HD;
    const size_t koff = ((size_t)(b * SEQ) << 12) + (size_t)h * HD;

#pragma unroll
    for (int j = 0; j < 8; j++) {
        int q = tid + 256 * j;
        int r = q >> 4, dt = q & 15;
        int srow = 2 * r + (dt >> 3);
        uint32_t adr = srow * 128 + (uint32_t)((((dt & 7)) ^ (srow & 7)) * 16);
        const size_t go = qoff + ((size_t)r << 12) + dt * 8;
        CP16(smb + AT_Q  + adr, (const char*)(g_Qh + go));
        CP16(smb + AT_QL + adr, (const char*)(g_Ql + go));
    }

#define ISSUE_KV(kt, st) do {                                                  \
        const size_t kb_ = koff + ((size_t)((kt) * 64) << 12);                 \
        const uint32_t sb_ = smb + AT_ST + (st) * AT_STSZ;                     \
        _Pragma("unroll")                                                      \
        for (int j = 0; j < 4; j++) {                                          \
            int q_ = tid + 256 * j;                                            \
            int r_ = q_ >> 4, dt_ = q_ & 15;                                   \
            int sr_ = 2 * r_ + (dt_ >> 3);                                     \
            uint32_t ad_ = sr_ * 128 + (uint32_t)(((dt_ & 7) ^ (sr_ & 7)) * 16); \
            const size_t g_ = kb_ + ((size_t)r_ << 12) + dt_ * 8;              \
            CP16(sb_ + ad_,         (const char*)(g_Kh + g_));                 \
            CP16(sb_ + 16384 + ad_, (const char*)(g_Kl + g_));                 \
            CP16(sb_ + 32768 + ad_, (const char*)(g_Vh + g_));                 \
            CP16(sb_ + 49152 + ad_, (const char*)(g_Vl + g_));                 \
        }                                                                      \
        CP_COMMIT();                                                           \
    } while (0)

    ISSUE_KV(0, 0);

    float o[16][4];
#pragma unroll
    for (int i = 0; i < 16; i++)
#pragma unroll
        for (int j = 0; j < 4; j++) o[i][j] = 0.0f;
    float m[2] = {-1e30f, -1e30f}, lsum[2] = {0.0f, 0.0f};

    const int ktiles = 2 * qt + 2;
    const int ar = wid * 16 + (lane & 15);
    const int akh = lane >> 4;

    for (int kt = 0; kt < ktiles; kt++) {
        const int st = kt & 1;
        if (kt + 1 < ktiles) { ISSUE_KV(kt + 1, st ^ 1); CP_WAIT1(); }
        else                 { CP_WAIT0(); }
        __syncthreads();

        const uint32_t sQh = smb + AT_Q, sQl = smb + AT_QL;
        const uint32_t sKh = smb + AT_ST + st * AT_STSZ;
        const uint32_t sKl = sKh + 16384, sVh = sKh + 32768, sVl = sKh + 49152;

        // ---- S = Q K^T (3-term, pass-major) ----
        float sc[8][4];
#pragma unroll
        for (int t = 0; t < 8; t++)
#pragma unroll
            for (int j = 0; j < 4; j++) sc[t][j] = 0.0f;

#pragma unroll
        for (int ks = 0; ks < 8; ks++) {
            const int qs = 2 * ar + (ks >> 2);
            const uint32_t aadr = qs * 128 +
                (uint32_t)(((((ks & 3) * 2 + akh)) ^ (qs & 7)) * 16);
            uint32_t qh[4], ql[4];
            LDSM4(qh[0], qh[1], qh[2], qh[3], sQh + aadr);
            LDSM4(ql[0], ql[1], ql[2], ql[3], sQl + aadr);
            uint32_t kh4[4][4], kl4[4][4];
#pragma unroll
            for (int ntp = 0; ntp < 4; ntp++) {
                const int kr = ((lane >> 4) ? (2 * ntp + 1) : (2 * ntp)) * 8 + (lane & 7);
                const int kkh = (lane >> 3) & 1;
                const int ksr = 2 * kr + (ks >> 2);
                const uint32_t kadr = ksr * 128 +
                    (uint32_t)(((((ks & 3) * 2 + kkh)) ^ (ksr & 7)) * 16);
                LDSM4(kh4[ntp][0], kh4[ntp][1], kh4[ntp][2], kh4[ntp][3], sKh + kadr);
                LDSM4(kl4[ntp][0], kl4[ntp][1], kl4[ntp][2], kl4[ntp][3], sKl + kadr);
            }
#pragma unroll
            for (int ntp = 0; ntp < 4; ntp++) {
                MMA16816(sc[2*ntp],   qh[0], qh[1], qh[2], qh[3], kh4[ntp][0], kh4[ntp][1]);
                MMA16816(sc[2*ntp+1], qh[0], qh[1], qh[2], qh[3], kh4[ntp][2], kh4[ntp][3]);
            }
#pragma unroll
            for (int ntp = 0; ntp < 4; ntp++) {
                MMA16816(sc[2*ntp],   qh[0], qh[1], qh[2], qh[3], kl4[ntp][0], kl4[ntp][1]);
                MMA16816(sc[2*ntp+1], qh[0], qh[1], qh[2], qh[3], kl4[ntp][2], kl4[ntp][3]);
            }
#pragma unroll
            for (int ntp = 0; ntp < 4; ntp++) {
                MMA16816(sc[2*ntp],   ql[0], ql[1], ql[2], ql[3], kh4[ntp][0], kh4[ntp][1]);
                MMA16816(sc[2*ntp+1], ql[0], ql[1], ql[2], ql[3], kh4[ntp][2], kh4[ntp][3]);
            }
        }

        // ---- causal mask ----
        const int k0 = kt * 64;
        if (k0 + 63 > q0) {
            const int rb = q0 + wid * 16 + (lane >> 2);
#pragma unroll
            for (int t = 0; t < 8; t++) {
                const int cb = k0 + t * 8 + (lane & 3) * 2;
                if (cb     > rb)     sc[t][0] = -1e30f;
                if (cb + 1 > rb)     sc[t][1] = -1e30f;
                if (cb     > rb + 8) sc[t][2] = -1e30f;
                if (cb + 1 > rb + 8) sc[t][3] = -1e30f;
            }
        }

        // ---- online softmax ----
#pragma unroll
        for (int rh = 0; rh < 2; rh++) {
            float mx = -1e30f;
#pragma unroll
            for (int t = 0; t < 8; t++)
                mx = fmaxf(mx, fmaxf(sc[t][2*rh], sc[t][2*rh+1]));
            mx = fmaxf(mx, __shfl_xor_sync(0xffffffffu, mx, 1));
            mx = fmaxf(mx, __shfl_xor_sync(0xffffffffu, mx, 2));
            const float mnew = fmaxf(m[rh], mx);
            const float alpha = __expf(m[rh] - mnew);
            float s = 0.0f;
#pragma unroll
            for (int t = 0; t < 8; t++) {
                float p0 = __expf(sc[t][2*rh]   - mnew);
                float p1 = __expf(sc[t][2*rh+1] - mnew);
                sc[t][2*rh] = p0; sc[t][2*rh+1] = p1;
                s += p0 + p1;
            }
            s += __shfl_xor_sync(0xffffffffu, s, 1);
            s += __shfl_xor_sync(0xffffffffu, s, 2);
            lsum[rh] = lsum[rh] * alpha + s;
            m[rh] = mnew;
#pragma unroll
            for (int dt = 0; dt < 16; dt++) {
                o[dt][2*rh]   *= alpha;
                o[dt][2*rh+1] *= alpha;
            }
        }

        // ---- O += P V (3-term; np pairs, pass-major, chain distance 4) ----
#pragma unroll
        for (int kj = 0; kj < 4; kj++) {
            uint32_t ph[4], pl[4];
#pragma unroll
            for (int u = 0; u < 4; u++) {
                const float* sp = sc[2 * kj + (u >> 1)];
                const float v0 = sp[(u & 1) * 2], v1 = sp[(u & 1) * 2 + 1];
                __nv_bfloat16 h0 = __float2bfloat16(v0), h1 = __float2bfloat16(v1);
                __nv_bfloat162 hp; hp.x = h0; hp.y = h1;
                ph[u] = *(uint32_t*)&hp;
                __nv_bfloat162 lp;
                lp.x = __float2bfloat16(v0 - __bfloat162float(h0));
                lp.y = __float2bfloat16(v1 - __bfloat162float(h1));
                pl[u] = *(uint32_t*)&lp;
            }
            const int jr = kj * 16 + (lane & 7) + (((lane >> 3) & 1) << 3);
#pragma unroll
            for (int npp = 0; npp < 4; npp++) {
                const int np0 = 2 * npp, np1 = 2 * npp + 1;
                uint32_t vhA[4], vlA[4], vhB[4], vlB[4];
                {
                    const int dtc = 2 * np0 + (lane >> 4);
                    const int vsr = 2 * jr + (dtc >> 3);
                    const uint32_t vadr = vsr * 128 +
                        (uint32_t)((((dtc & 7)) ^ (vsr & 7)) * 16);
                    LDSM4T(vhA[0], vhA[1], vhA[2], vhA[3], sVh + vadr);
                    LDSM4T(vlA[0], vlA[1], vlA[2], vlA[3], sVl + vadr);
                }
                {
                    const int dtc = 2 * np1 + (lane >> 4);
                    const int vsr = 2 * jr + (dtc >> 3);
                    const uint32_t vadr = vsr * 128 +
                        (uint32_t)((((dtc & 7)) ^ (vsr & 7)) * 16);
                    LDSM4T(vhB[0], vhB[1], vhB[2], vhB[3], sVh + vadr);
                    LDSM4T(vlB[0], vlB[1], vlB[2], vlB[3], sVl + vadr);
                }
                // pass hh
                MMA16816(o[2*np0],   ph[0], ph[1], ph[2], ph[3], vhA[0], vhA[1]);
                MMA16816(o[2*np0+1], ph[0], ph[1], ph[2], ph[3], vhA[2], vhA[3]);
                MMA16816(o[2*np1],   ph[0], ph[1], ph[2], ph[3], vhB[0], vhB[1]);
                MMA16816(o[2*np1+1], ph[0], ph[1], ph[2], ph[3], vhB[2], vhB[3]);
                // pass hl
                MMA16816(o[2*np0],   ph[0], ph[1], ph[2], ph[3], vlA[0], vlA[1]);
                MMA16816(o[2*np0+1], ph[0], ph[1], ph[2], ph[3], vlA[2], vlA[3]);
                MMA16816(o[2*np1],   ph[0], ph[1], ph[2], ph[3], vlB[0], vlB[1]);
                MMA16816(o[2*np1+1], ph[0], ph[1], ph[2], ph[3], vlB[2], vlB[3]);
                // pass lh
                MMA16816(o[2*np0],   pl[0], pl[1], pl[2], pl[3], vhA[0], vhA[1]);
                MMA16816(o[2*np0+1], pl[0], pl[1], pl[2], pl[3], vhA[2], vhA[3]);
                MMA16816(o[2*np1],   pl[0], pl[1], pl[2], pl[3], vhB[0], vhB[1]);
                MMA16816(o[2*np1+1], pl[0], pl[1], pl[2], pl[3], vhB[2], vhB[3]);
            }
        }
        __syncthreads();
    }

    // ---- epilogue: normalize + bf16 hi/lo split ----
#pragma unroll
    for (int rh = 0; rh < 2; rh++) {
        const float inv = 1.0f / lsum[rh];
        const int row = q0 + wid * 16 + (lane >> 2) + rh * 8;
        const size_t ro = ((size_t)(b * SEQ + row) << 12) + (size_t)h * HD
                          + (lane & 3) * 2;
#pragma unroll
        for (int dt = 0; dt < 16; dt++) {
            const float v0 = o[dt][2*rh] * inv, v1 = o[dt][2*rh+1] * inv;
            __nv_bfloat16 h0 = __float2bfloat16(v0), h1 = __float2bfloat16(v1);
            __nv_bfloat162 hp; hp.x = h0; hp.y = h1;
            *(__nv_bfloat162*)&g_Oh[ro + dt * 8] = hp;
            __nv_bfloat162 lp;
            lp.x = __float2bfloat16(v0 - __bfloat162float(h0));
            lp.y = __float2bfloat16(v1 - __bfloat162float(h1));
            *(__nv_bfloat162*)&g_Ol[ro + dt * 8] = lp;
        }
    }
}

// ---------------- launcher -------------------------------------------------
extern "C" void kernel_launch(void* const* d_in, const int* in_sizes, int n_in,
                              void* d_out, int out_size) {
    const float* x    = (const float*)d_in[0];
    const float* wq_w = (const float*)d_in[1];
    const float* wq_a = (const float*)d_in[2];
    const float* wq_b = (const float*)d_in[3];
    const float* wk_w = (const float*)d_in[4];
    const float* wv_w = (const float*)d_in[5];
    const float* wv_a = (const float*)d_in[6];
    const float* wv_b = (const float*)d_in[7];
    const float* wo_w = (const float*)d_in[8];
    const float* fc   = (const float*)d_in[9];
    const float* fs   = (const float*)d_in[10];
    float* out = (float*)d_out;

    __nv_bfloat16 *xh, *xl, *Wqh, *Wql, *Wkh, *Wkl, *Wvh, *Wvl, *Woh, *Wol;
    __nv_bfloat16 *Qh, *Ql, *Kh, *Kl, *Vh, *Vl, *Oh, *Ol;
    cudaGetSymbolAddress((void**)&xh, g_xh);   cudaGetSymbolAddress((void**)&xl, g_xl);
    cudaGetSymbolAddress((void**)&Wqh, g_Wqh); cudaGetSymbolAddress((void**)&Wql, g_Wql);
    cudaGetSymbolAddress((void**)&Wkh, g_Wkh); cudaGetSymbolAddress((void**)&Wkl, g_Wkl);
    cudaGetSymbolAddress((void**)&Wvh, g_Wvh); cudaGetSymbolAddress((void**)&Wvl, g_Wvl);
    cudaGetSymbolAddress((void**)&Woh, g_Woh); cudaGetSymbolAddress((void**)&Wol, g_Wol);
    cudaGetSymbolAddress((void**)&Qh, g_Qh);   cudaGetSymbolAddress((void**)&Ql, g_Ql);
    cudaGetSymbolAddress((void**)&Kh, g_Kh);   cudaGetSymbolAddress((void**)&Kl, g_Kl);
    cudaGetSymbolAddress((void**)&Vh, g_Vh);   cudaGetSymbolAddress((void**)&Vl, g_Vl);
    cudaGetSymbolAddress((void**)&Oh, g_Oh);   cudaGetSymbolAddress((void**)&Ol, g_Ol);

    cudaFuncSetAttribute(gemm_mma3<0>, cudaFuncAttributeMaxDynamicSharedMemorySize, GEMM_SMEM);
    cudaFuncSetAttribute(gemm_mma3<1>, cudaFuncAttributeMaxDynamicSharedMemorySize, GEMM_SMEM);
    cudaFuncSetAttribute(gemm_mma3<2>, cudaFuncAttributeMaxDynamicSharedMemorySize, GEMM_SMEM);
    cudaFuncSetAttribute(gemm_mma3<3>, cudaFuncAttributeMaxDynamicSharedMemorySize, GEMM_SMEM);
    cudaFuncSetAttribute(attn_mma, cudaFuncAttributeMaxDynamicSharedMemorySize, ATTN_SMEM);

    // 1) fold LoRA + split to bf16 hi/lo
    merge_split<<<(D * D) / 256, 256>>>(wq_w, wq_a, wq_b, Wqh, Wql);
    merge_split<<<(D * D) / 256, 256>>>(wv_w, wv_a, wv_b, Wvh, Wvl);
    split8<<<(D * D) / 8 / 256, 256>>>(wk_w, Wkh, Wkl);
    split8<<<(D * D) / 8 / 256, 256>>>(wo_w, Woh, Wol);
    split8<<<((size_t)BSR * D) / 8 / 256, 256>>>(x, xh, xl);

    // 2) projections -> bf16 hi/lo; RoPE fused (K), RoPE+scale fused (Q)
    dim3 g(D / 128, BSR / 128);
    gemm_mma3<3><<<g, 256, GEMM_SMEM>>>(xh, xl, Wqh, Wql, nullptr, Qh, Ql, fc, fs);
    gemm_mma3<2><<<g, 256, GEMM_SMEM>>>(xh, xl, Wkh, Wkl, nullptr, Kh, Kl, fc, fs);
    gemm_mma3<1><<<g, 256, GEMM_SMEM>>>(xh, xl, Wvh, Wvl, nullptr, Vh, Vl, fc, fs);

    // 3) MMA flash attention -> g_Oh/g_Ol
    attn_mma<<<dim3(SEQ / 128, NH, 4), 256, ATTN_SMEM>>>();

    // 4) output projection (fp32 out)
    gemm_mma3<0><<<g, 256, GEMM_SMEM>>>(Oh, Ol, Woh, Wol, out, nullptr, nullptr, fc, fs);
}

// round 11
// speedup vs baseline: 1.3354x; 1.3354x over previous
#include <cuda_runtime.h>
#include <cuda_bf16.h>
#include <cuda_fp16.h>
#include <cstdint>

#define D   4096
#define BSR 4096
#define SEQ 1024
#define NH  32
#define HD  128
#define LR  16
#define SCALE 0.08838834764831845f

// ------------------------- device scratch ---------------------------------
__device__ __half g_xh[(size_t)BSR * D], g_xl[(size_t)BSR * D];
__device__ __half g_Wq[(size_t)D * D], g_Wk[(size_t)D * D];
__device__ __half g_Wv[(size_t)D * D], g_Wo[(size_t)D * D];
__device__ __nv_bfloat16 g_Qh[(size_t)BSR * D], g_Ql[(size_t)BSR * D];
__device__ __nv_bfloat16 g_Kh[(size_t)BSR * D], g_Kl[(size_t)BSR * D];
__device__ __nv_bfloat16 g_Vh[(size_t)BSR * D], g_Vl[(size_t)BSR * D];
__device__ __half g_Oh[(size_t)BSR * D], g_Ol[(size_t)BSR * D];

// ------------------------- PTX helpers (base-target only) ------------------
__device__ __forceinline__ uint32_t smem_to_u32(const void* p) {
    uint32_t a;
    asm("{ .reg .u64 t; cvta.to.shared.u64 t, %1; cvt.u32.u64 %0, t; }"
        : "=r"(a) : "l"(p));
    return a;
}
#define CP16(dst, src) \
    asm volatile("cp.async.cg.shared.global [%0], [%1], 16;" \
                 :: "r"(dst), "l"(src))
#define CP_COMMIT() asm volatile("cp.async.commit_group;" ::: "memory")
#define CP_WAIT1()  asm volatile("cp.async.wait_group 1;" ::: "memory")
#define CP_WAIT0()  asm volatile("cp.async.wait_group 0;" ::: "memory")

#define LDSM4(r0, r1, r2, r3, addr) \
    asm volatile("ldmatrix.sync.aligned.m8n8.x4.shared.b16 {%0,%1,%2,%3}, [%4];" \
                 : "=r"(r0), "=r"(r1), "=r"(r2), "=r"(r3) : "r"(addr))
#define LDSM4T(r0, r1, r2, r3, addr) \
    asm volatile("ldmatrix.sync.aligned.m8n8.x4.trans.shared.b16 {%0,%1,%2,%3}, [%4];" \
                 : "=r"(r0), "=r"(r1), "=r"(r2), "=r"(r3) : "r"(addr))
#define LDSM2(r0, r1, addr) \
    asm volatile("ldmatrix.sync.aligned.m8n8.x2.shared.b16 {%0,%1}, [%2];" \
                 : "=r"(r0), "=r"(r1) : "r"(addr))
// bf16 mma (attention)
#define MMA16816(c, a0, a1, a2, a3, b0, b1) \
    asm volatile("mma.sync.aligned.m16n8k16.row.col.f32.bf16.bf16.f32 " \
                 "{%0,%1,%2,%3}, {%4,%5,%6,%7}, {%8,%9}, {%0,%1,%2,%3};" \
                 : "+f"((c)[0]), "+f"((c)[1]), "+f"((c)[2]), "+f"((c)[3]) \
                 : "r"(a0), "r"(a1), "r"(a2), "r"(a3), "r"(b0), "r"(b1))
// fp16 mma (projection GEMMs)
#define MMAF16(c, a0, a1, a2, a3, b0, b1) \
    asm volatile("mma.sync.aligned.m16n8k16.row.col.f32.f16.f16.f32 " \
                 "{%0,%1,%2,%3}, {%4,%5,%6,%7}, {%8,%9}, {%0,%1,%2,%3};" \
                 : "+f"((c)[0]), "+f"((c)[1]), "+f"((c)[2]), "+f"((c)[3]) \
                 : "r"(a0), "r"(a1), "r"(a2), "r"(a3), "r"(b0), "r"(b1))

// ------------------------- fused prep kernels ------------------------------
// LoRA merge -> fp16 weights; one launch covers Wq (sel 0) and Wv (sel 1).
__global__ void prep_merge(const float* __restrict__ wq_w,
                           const float* __restrict__ wq_a,
                           const float* __restrict__ wq_b,
                           const float* __restrict__ wv_w,
                           const float* __restrict__ wv_a,
                           const float* __restrict__ wv_b,
                           __half* __restrict__ Wq,
                           __half* __restrict__ Wv) {
    const int sel = blockIdx.x >> 16;            // 65536 blocks per matrix
    const int idx = ((blockIdx.x & 65535) << 8) + threadIdx.x;
    const float* w = sel ? wv_w : wq_w;
    const float* a = sel ? wv_a : wq_a;
    const float* b = sel ? wv_b : wq_b;
    __half* o      = sel ? Wv   : Wq;
    const int n = idx >> 12, k = idx & (D - 1);
    float acc = w[idx];
#pragma unroll
    for (int r = 0; r < LR; r++)
        acc += 2.0f * __ldg(&b[n * LR + r]) * __ldg(&a[r * D + k]);
    o[idx] = __float2half_rn(acc);
}

// sel 0: wk -> fp16; sel 1: wo -> fp16; sel 2: x -> fp16 hi/lo split.
__global__ void prep_split(const float* __restrict__ wk_w,
                           const float* __restrict__ wo_w,
                           const float* __restrict__ x,
                           __half* __restrict__ Wk,
                           __half* __restrict__ Wo,
                           __half* __restrict__ xh,
                           __half* __restrict__ xl) {
    const int sel = blockIdx.x >> 13;            // 8192 blocks per section
    const size_t i = (((size_t)(blockIdx.x & 8191) << 8) + threadIdx.x) * 8;
    const float* src = sel == 0 ? wk_w : (sel == 1 ? wo_w : x);
    float v[8];
    *(float4*)&v[0] = *(const float4*)(src + i);
    *(float4*)&v[4] = *(const float4*)(src + i + 4);
    __half h[8];
#pragma unroll
    for (int j = 0; j < 8; j++) h[j] = __float2half_rn(v[j]);
    if (sel == 2) {
        __half l[8];
#pragma unroll
        for (int j = 0; j < 8; j++)
            l[j] = __float2half_rn(v[j] - __half2float(h[j]));
        *(float4*)(xh + i) = *(float4*)h;
        *(float4*)(xl + i) = *(float4*)l;
    } else {
        __half* dst = sel == 0 ? Wk : Wo;
        *(float4*)(dst + i) = *(float4*)h;
    }
}

// ------------- fp16 2-term GEMM (NT) on mma.sync tensor cores --------------
// C = Ah*B^T + Al*B^T, A = Ah + Al (fp16 split, near-exact), B = fp16(W).
// BM=BN=128, BK=64, 256 thr (8 warps 2x4). 3-stage cp.async, 1 barrier/chunk.
// MODE: 0 = fp32 store (final out), 1 = bf16 hi/lo split store (V),
//       2 = RoPE + split (K),       3 = RoPE + scale + split (Q).
#define GTILE   16384
#define GSTAGE  (3 * GTILE)
#define NSTAGE  3
#define GEMM_SMEM (NSTAGE * GSTAGE)
#define NCHUNK  64   // D / BK

template <int MODE>
__global__ void __launch_bounds__(256, 1) gemm_f16x2(
    const __half* __restrict__ Ah, const __half* __restrict__ Al,
    const __half* __restrict__ B,
    float* __restrict__ C,
    __nv_bfloat16* __restrict__ Ch, __nv_bfloat16* __restrict__ Cl,
    const float* __restrict__ fc, const float* __restrict__ fs) {
    extern __shared__ char smch[];
    const uint32_t smb = smem_to_u32(smch);
    const int tid = threadIdx.x, lane = tid & 31, wid = tid >> 5;
    const int warp_m = wid & 1;
    const int warp_n = wid >> 1;
    const int bm = blockIdx.y * 128, bn = blockIdx.x * 128;

    float acc[4][4][4];
#pragma unroll
    for (int i = 0; i < 4; i++)
#pragma unroll
        for (int j = 0; j < 4; j++)
#pragma unroll
            for (int k = 0; k < 4; k++) acc[i][j][k] = 0.0f;

    const int r0 = tid >> 3, c0 = tid & 7;
    const uint32_t dst0 = r0 * 128 + (uint32_t)((c0 ^ (r0 & 7)) * 16);
    const __half* gAh = Ah + ((size_t)(bm + r0) << 12) + c0 * 8;
    const __half* gAl = Al + ((size_t)(bm + r0) << 12) + c0 * 8;
    const __half* gB  = B  + ((size_t)(bn + r0) << 12) + c0 * 8;

#define ISSUE(ck, st) do {                                                     \
        const uint32_t sb_ = smb + (st) * GSTAGE + dst0;                       \
        const size_t go_ = (size_t)(ck) * 64;                                  \
        _Pragma("unroll")                                                      \
        for (int j = 0; j < 4; j++) {                                          \
            const uint32_t d_ = sb_ + j * 32 * 128;                            \
            const size_t s_ = go_ + ((size_t)j << 17);                         \
            CP16(d_,             (const char*)(gAh + s_));                     \
            CP16(d_ + GTILE,     (const char*)(gAl + s_));                     \
            CP16(d_ + 2 * GTILE, (const char*)(gB  + s_));                     \
        }                                                                      \
        CP_COMMIT();                                                           \
    } while (0)

    ISSUE(0, 0);
    ISSUE(1, 1);

    const int arow = warp_m * 64 + (lane & 15);
    const int akh  = lane >> 4;
    const int brow = warp_n * 32 + (lane & 7);
    const int bkh  = (lane >> 3) & 1;

    for (int ck = 0; ck < NCHUNK; ck++) {
        const int st = ck % NSTAGE;
        if (ck + 2 >= NCHUNK) { CP_WAIT0(); } else { CP_WAIT1(); }
        __syncthreads();
        if (ck + 2 < NCHUNK) ISSUE(ck + 2, (ck + 2) % NSTAGE);

        const uint32_t sAh = smb + st * GSTAGE;
        const uint32_t sAl = sAh + GTILE;
        const uint32_t sB  = sAh + 2 * GTILE;

#pragma unroll
        for (int ks = 0; ks < 4; ks++) {
            uint32_t ah[4][4], al[4][4], bb[4][2];
#pragma unroll
            for (int mt = 0; mt < 4; mt++) {
                const int r = arow + mt * 16;
                const uint32_t adr = r * 128 + (((ks * 2 + akh) ^ (r & 7)) * 16);
                LDSM4(ah[mt][0], ah[mt][1], ah[mt][2], ah[mt][3], sAh + adr);
                LDSM4(al[mt][0], al[mt][1], al[mt][2], al[mt][3], sAl + adr);
            }
#pragma unroll
            for (int nt = 0; nt < 4; nt++) {
                const int r = brow + nt * 8;
                const uint32_t adr = r * 128 + (((ks * 2 + bkh) ^ (r & 7)) * 16);
                LDSM2(bb[nt][0], bb[nt][1], sB + adr);
            }
#pragma unroll
            for (int mt = 0; mt < 4; mt++)
#pragma unroll
                for (int nt = 0; nt < 4; nt++)
                    MMAF16(acc[mt][nt], ah[mt][0], ah[mt][1], ah[mt][2], ah[mt][3],
                           bb[nt][0], bb[nt][1]);
#pragma unroll
            for (int mt = 0; mt < 4; mt++)
#pragma unroll
                for (int nt = 0; nt < 4; nt++)
                    MMAF16(acc[mt][nt], al[mt][0], al[mt][1], al[mt][2], al[mt][3],
                           bb[nt][0], bb[nt][1]);
        }
    }

    // epilogue
#pragma unroll
    for (int mt = 0; mt < 4; mt++) {
        const int row = bm + warp_m * 64 + mt * 16 + (lane >> 2);
#pragma unroll
        for (int nt = 0; nt < 4; nt++) {
            const int col = bn + warp_n * 32 + nt * 8 + (lane & 3) * 2;
            float v0 = acc[mt][nt][0], v1 = acc[mt][nt][1];
            float v2 = acc[mt][nt][2], v3 = acc[mt][nt][3];
            if (MODE >= 2) {
                const int i = (col & (HD - 1)) >> 1;
                const int s1 = row & (SEQ - 1);
                const int s2 = (row + 8) & (SEQ - 1);
                const float c1 = __ldg(&fc[s1 * 64 + i]), n1 = __ldg(&fs[s1 * 64 + i]);
                const float c2 = __ldg(&fc[s2 * 64 + i]), n2 = __ldg(&fs[s2 * 64 + i]);
                float t;
                t  = v0 * c1 - v1 * n1; v1 = v0 * n1 + v1 * c1; v0 = t;
                t  = v2 * c2 - v3 * n2; v3 = v2 * n2 + v3 * c2; v2 = t;
            }
            if (MODE == 3) { v0 *= SCALE; v1 *= SCALE; v2 *= SCALE; v3 *= SCALE; }
            if (MODE == 0) {
                *(float2*)&C[(size_t)row * D + col]       = make_float2(v0, v1);
                *(float2*)&C[(size_t)(row + 8) * D + col] = make_float2(v2, v3);
            } else {
                __nv_bfloat16 h0 = __float2bfloat16(v0), h1 = __float2bfloat16(v1);
                __nv_bfloat162 hp; hp.x = h0; hp.y = h1;
                *(__nv_bfloat162*)&Ch[(size_t)row * D + col] = hp;
                __nv_bfloat162 lp;
                lp.x = __float2bfloat16(v0 - __bfloat162float(h0));
                lp.y = __float2bfloat16(v1 - __bfloat162float(h1));
                *(__nv_bfloat162*)&Cl[(size_t)row * D + col] = lp;
                __nv_bfloat16 h2 = __float2bfloat16(v2), h3 = __float2bfloat16(v3);
                __nv_bfloat162 hq; hq.x = h2; hq.y = h3;
                *(__nv_bfloat162*)&Ch[(size_t)(row + 8) * D + col] = hq;
                __nv_bfloat162 lq;
                lq.x = __float2bfloat16(v2 - __bfloat162float(h2));
                lq.y = __float2bfloat16(v3 - __bfloat162float(h3));
                *(__nv_bfloat162*)&Cl[(size_t)(row + 8) * D + col] = lq;
            }
        }
    }
}

// ---------------- MMA flash attention (bf16 hi/lo 3-term, causal) ----------
// Validated R9/R10 kernel; epilogue now emits fp16 hi/lo O for the O-GEMM.
#define AT_Q    0
#define AT_QL   32768
#define AT_ST   65536
#define AT_STSZ 65536   // Kh | Kl | Vh | Vl (16KB each)
#define ATTN_SMEM (AT_ST + 2 * AT_STSZ)

__global__ void __launch_bounds__(256, 1) attn_mma() {
    extern __shared__ char smc[];
    const uint32_t smb = smem_to_u32(smc);
    const int b = blockIdx.z, h = blockIdx.y, qt = blockIdx.x;
    const int q0 = qt * 128;
    const int tid = threadIdx.x, lane = tid & 31, wid = tid >> 5;

    const size_t qoff = ((size_t)(b * SEQ + q0) << 12) + (size_t)h * HD;
    const size_t koff = ((size_t)(b * SEQ) << 12) + (size_t)h * HD;

#pragma unroll
    for (int j = 0; j < 8; j++) {
        int q = tid + 256 * j;
        int r = q >> 4, dt = q & 15;
        int srow = 2 * r + (dt >> 3);
        uint32_t adr = srow * 128 + (uint32_t)((((dt & 7)) ^ (srow & 7)) * 16);
        const size_t go = qoff + ((size_t)r << 12) + dt * 8;
        CP16(smb + AT_Q  + adr, (const char*)(g_Qh + go));
        CP16(smb + AT_QL + adr, (const char*)(g_Ql + go));
    }

#define ISSUE_KV(kt, st) do {                                                  \
        const size_t kb_ = koff + ((size_t)((kt) * 64) << 12);                 \
        const uint32_t sb_ = smb + AT_ST + (st) * AT_STSZ;                     \
        _Pragma("unroll")                                                      \
        for (int j = 0; j < 4; j++) {                                          \
            int q_ = tid + 256 * j;                                            \
            int r_ = q_ >> 4, dt_ = q_ & 15;                                   \
            int sr_ = 2 * r_ + (dt_ >> 3);                                     \
            uint32_t ad_ = sr_ * 128 + (uint32_t)(((dt_ & 7) ^ (sr_ & 7)) * 16); \
            const size_t g_ = kb_ + ((size_t)r_ << 12) + dt_ * 8;              \
            CP16(sb_ + ad_,         (const char*)(g_Kh + g_));                 \
            CP16(sb_ + 16384 + ad_, (const char*)(g_Kl + g_));                 \
            CP16(sb_ + 32768 + ad_, (const char*)(g_Vh + g_));                 \
            CP16(sb_ + 49152 + ad_, (const char*)(g_Vl + g_));                 \
        }                                                                      \
        CP_COMMIT();                                                           \
    } while (0)

    ISSUE_KV(0, 0);

    float o[16][4];
#pragma unroll
    for (int i = 0; i < 16; i++)
#pragma unroll
        for (int j = 0; j < 4; j++) o[i][j] = 0.0f;
    float m[2] = {-1e30f, -1e30f}, lsum[2] = {0.0f, 0.0f};

    const int ktiles = 2 * qt + 2;
    const int ar = wid * 16 + (lane & 15);
    const int akh = lane >> 4;

    for (int kt = 0; kt < ktiles; kt++) {
        const int st = kt & 1;
        if (kt + 1 < ktiles) { ISSUE_KV(kt + 1, st ^ 1); CP_WAIT1(); }
        else                 { CP_WAIT0(); }
        __syncthreads();

        const uint32_t sQh = smb + AT_Q, sQl = smb + AT_QL;
        const uint32_t sKh = smb + AT_ST + st * AT_STSZ;
        const uint32_t sKl = sKh + 16384, sVh = sKh + 32768, sVl = sKh + 49152;

        float sc[8][4];
#pragma unroll
        for (int t = 0; t < 8; t++)
#pragma unroll
            for (int j = 0; j < 4; j++) sc[t][j] = 0.0f;

#pragma unroll
        for (int ks = 0; ks < 8; ks++) {
            const int qs = 2 * ar + (ks >> 2);
            const uint32_t aadr = qs * 128 +
                (uint32_t)(((((ks & 3) * 2 + akh)) ^ (qs & 7)) * 16);
            uint32_t qh[4], ql[4];
            LDSM4(qh[0], qh[1], qh[2], qh[3], sQh + aadr);
            LDSM4(ql[0], ql[1], ql[2], ql[3], sQl + aadr);
            uint32_t kh4[4][4], kl4[4][4];
#pragma unroll
            for (int ntp = 0; ntp < 4; ntp++) {
                const int kr = ((lane >> 4) ? (2 * ntp + 1) : (2 * ntp)) * 8 + (lane & 7);
                const int kkh = (lane >> 3) & 1;
                const int ksr = 2 * kr + (ks >> 2);
                const uint32_t kadr = ksr * 128 +
                    (uint32_t)(((((ks & 3) * 2 + kkh)) ^ (ksr & 7)) * 16);
                LDSM4(kh4[ntp][0], kh4[ntp][1], kh4[ntp][2], kh4[ntp][3], sKh + kadr);
                LDSM4(kl4[ntp][0], kl4[ntp][1], kl4[ntp][2], kl4[ntp][3], sKl + kadr);
            }
#pragma unroll
            for (int ntp = 0; ntp < 4; ntp++) {
                MMA16816(sc[2*ntp],   qh[0], qh[1], qh[2], qh[3], kh4[ntp][0], kh4[ntp][1]);
                MMA16816(sc[2*ntp+1], qh[0], qh[1], qh[2], qh[3], kh4[ntp][2], kh4[ntp][3]);
            }
#pragma unroll
            for (int ntp = 0; ntp < 4; ntp++) {
                MMA16816(sc[2*ntp],   qh[0], qh[1], qh[2], qh[3], kl4[ntp][0], kl4[ntp][1]);
                MMA16816(sc[2*ntp+1], qh[0], qh[1], qh[2], qh[3], kl4[ntp][2], kl4[ntp][3]);
            }
#pragma unroll
            for (int ntp = 0; ntp < 4; ntp++) {
                MMA16816(sc[2*ntp],   ql[0], ql[1], ql[2], ql[3], kh4[ntp][0], kh4[ntp][1]);
                MMA16816(sc[2*ntp+1], ql[0], ql[1], ql[2], ql[3], kh4[ntp][2], kh4[ntp][3]);
            }
        }

        const int k0 = kt * 64;
        if (k0 + 63 > q0) {
            const int rb = q0 + wid * 16 + (lane >> 2);
#pragma unroll
            for (int t = 0; t < 8; t++) {
                const int cb = k0 + t * 8 + (lane & 3) * 2;
                if (cb     > rb)     sc[t][0] = -1e30f;
                if (cb + 1 > rb)     sc[t][1] = -1e30f;
                if (cb     > rb + 8) sc[t][2] = -1e30f;
                if (cb + 1 > rb + 8) sc[t][3] = -1e30f;
            }
        }

#pragma unroll
        for (int rh = 0; rh < 2; rh++) {
            float mx = -1e30f;
#pragma unroll
            for (int t = 0; t < 8; t++)
                mx = fmaxf(mx, fmaxf(sc[t][2*rh], sc[t][2*rh+1]));
            mx = fmaxf(mx, __shfl_xor_sync(0xffffffffu, mx, 1));
            mx = fmaxf(mx, __shfl_xor_sync(0xffffffffu, mx, 2));
            const float mnew = fmaxf(m[rh], mx);
            const float alpha = __expf(m[rh] - mnew);
            float s = 0.0f;
#pragma unroll
            for (int t = 0; t < 8; t++) {
                float p0 = __expf(sc[t][2*rh]   - mnew);
                float p1 = __expf(sc[t][2*rh+1] - mnew);
                sc[t][2*rh] = p0; sc[t][2*rh+1] = p1;
                s += p0 + p1;
            }
            s += __shfl_xor_sync(0xffffffffu, s, 1);
            s += __shfl_xor_sync(0xffffffffu, s, 2);
            lsum[rh] = lsum[rh] * alpha + s;
            m[rh] = mnew;
#pragma unroll
            for (int dt = 0; dt < 16; dt++) {
                o[dt][2*rh]   *= alpha;
                o[dt][2*rh+1] *= alpha;
            }
        }

#pragma unroll
        for (int kj = 0; kj < 4; kj++) {
            uint32_t ph[4], pl[4];
#pragma unroll
            for (int u = 0; u < 4; u++) {
                const float* sp = sc[2 * kj + (u >> 1)];
                const float v0 = sp[(u & 1) * 2], v1 = sp[(u & 1) * 2 + 1];
                __nv_bfloat16 h0 = __float2bfloat16(v0), h1 = __float2bfloat16(v1);
                __nv_bfloat162 hp; hp.x = h0; hp.y = h1;
                ph[u] = *(uint32_t*)&hp;
                __nv_bfloat162 lp;
                lp.x = __float2bfloat16(v0 - __bfloat162float(h0));
                lp.y = __float2bfloat16(v1 - __bfloat162float(h1));
                pl[u] = *(uint32_t*)&lp;
            }
            const int jr = kj * 16 + (lane & 7) + (((lane >> 3) & 1) << 3);
#pragma unroll
            for (int npp = 0; npp < 4; npp++) {
                const int np0 = 2 * npp, np1 = 2 * npp + 1;
                uint32_t vhA[4], vlA[4], vhB[4], vlB[4];
                {
                    const int dtc = 2 * np0 + (lane >> 4);
                    const int vsr = 2 * jr + (dtc >> 3);
                    const uint32_t vadr = vsr * 128 +
                        (uint32_t)((((dtc & 7)) ^ (vsr & 7)) * 16);
                    LDSM4T(vhA[0], vhA[1], vhA[2], vhA[3], sVh + vadr);
                    LDSM4T(vlA[0], vlA[1], vlA[2], vlA[3], sVl + vadr);
                }
                {
                    const int dtc = 2 * np1 + (lane >> 4);
                    const int vsr = 2 * jr + (dtc >> 3);
                    const uint32_t vadr = vsr * 128 +
                        (uint32_t)((((dtc & 7)) ^ (vsr & 7)) * 16);
                    LDSM4T(vhB[0], vhB[1], vhB[2], vhB[3], sVh + vadr);
                    LDSM4T(vlB[0], vlB[1], vlB[2], vlB[3], sVl + vadr);
                }
                MMA16816(o[2*np0],   ph[0], ph[1], ph[2], ph[3], vhA[0], vhA[1]);
                MMA16816(o[2*np0+1], ph[0], ph[1], ph[2], ph[3], vhA[2], vhA[3]);
                MMA16816(o[2*np1],   ph[0], ph[1], ph[2], ph[3], vhB[0], vhB[1]);
                MMA16816(o[2*np1+1], ph[0], ph[1], ph[2], ph[3], vhB[2], vhB[3]);
                MMA16816(o[2*np0],   ph[0], ph[1], ph[2], ph[3], vlA[0], vlA[1]);
                MMA16816(o[2*np0+1], ph[0], ph[1], ph[2], ph[3], vlA[2], vlA[3]);
                MMA16816(o[2*np1],   ph[0], ph[1], ph[2], ph[3], vlB[0], vlB[1]);
                MMA16816(o[2*np1+1], ph[0], ph[1], ph[2], ph[3], vlB[2], vlB[3]);
                MMA16816(o[2*np0],   pl[0], pl[1], pl[2], pl[3], vhA[0], vhA[1]);
                MMA16816(o[2*np0+1], pl[0], pl[1], pl[2], pl[3], vhA[2], vhA[3]);
                MMA16816(o[2*np1],   pl[0], pl[1], pl[2], pl[3], vhB[0], vhB[1]);
                MMA16816(o[2*np1+1], pl[0], pl[1], pl[2], pl[3], vhB[2], vhB[3]);
            }
        }
        __syncthreads();
    }

    // ---- epilogue: normalize + fp16 hi/lo split (feeds fp16 O-GEMM) ----
#pragma unroll
    for (int rh = 0; rh < 2; rh++) {
        const float inv = 1.0f / lsum[rh];
        const int row = q0 + wid * 16 + (lane >> 2) + rh * 8;
        const size_t ro = ((size_t)(b * SEQ + row) << 12) + (size_t)h * HD
                          + (lane & 3) * 2;
#pragma unroll
        for (int dt = 0; dt < 16; dt++) {
            const float v0 = o[dt][2*rh] * inv, v1 = o[dt][2*rh+1] * inv;
            __half h0 = __float2half_rn(v0), h1 = __float2half_rn(v1);
            __half2 hp; hp.x = h0; hp.y = h1;
            *(__half2*)&g_Oh[ro + dt * 8] = hp;
            __half2 lp;
            lp.x = __float2half_rn(v0 - __half2float(h0));
            lp.y = __float2half_rn(v1 - __half2float(h1));
            *(__half2*)&g_Ol[ro + dt * 8] = lp;
        }
    }
}

// ---------------- launcher -------------------------------------------------
extern "C" void kernel_launch(void* const* d_in, const int* in_sizes, int n_in,
                              void* d_out, int out_size) {
    const float* x    = (const float*)d_in[0];
    const float* wq_w = (const float*)d_in[1];
    const float* wq_a = (const float*)d_in[2];
    const float* wq_b = (const float*)d_in[3];
    const float* wk_w = (const float*)d_in[4];
    const float* wv_w = (const float*)d_in[5];
    const float* wv_a = (const float*)d_in[6];
    const float* wv_b = (const float*)d_in[7];
    const float* wo_w = (const float*)d_in[8];
    const float* fc   = (const float*)d_in[9];
    const float* fs   = (const float*)d_in[10];
    float* out = (float*)d_out;

    __half *xh, *xl, *Wq, *Wk, *Wv, *Wo, *Oh, *Ol;
    __nv_bfloat16 *Qh, *Ql, *Kh, *Kl, *Vh, *Vl;
    cudaGetSymbolAddress((void**)&xh, g_xh); cudaGetSymbolAddress((void**)&xl, g_xl);
    cudaGetSymbolAddress((void**)&Wq, g_Wq); cudaGetSymbolAddress((void**)&Wk, g_Wk);
    cudaGetSymbolAddress((void**)&Wv, g_Wv); cudaGetSymbolAddress((void**)&Wo, g_Wo);
    cudaGetSymbolAddress((void**)&Qh, g_Qh); cudaGetSymbolAddress((void**)&Ql, g_Ql);
    cudaGetSymbolAddress((void**)&Kh, g_Kh); cudaGetSymbolAddress((void**)&Kl, g_Kl);
    cudaGetSymbolAddress((void**)&Vh, g_Vh); cudaGetSymbolAddress((void**)&Vl, g_Vl);
    cudaGetSymbolAddress((void**)&Oh, g_Oh); cudaGetSymbolAddress((void**)&Ol, g_Ol);

    cudaFuncSetAttribute(gemm_f16x2<0>, cudaFuncAttributeMaxDynamicSharedMemorySize, GEMM_SMEM);
    cudaFuncSetAttribute(gemm_f16x2<1>, cudaFuncAttributeMaxDynamicSharedMemorySize, GEMM_SMEM);
    cudaFuncSetAttribute(gemm_f16x2<2>, cudaFuncAttributeMaxDynamicSharedMemorySize, GEMM_SMEM);
    cudaFuncSetAttribute(gemm_f16x2<3>, cudaFuncAttributeMaxDynamicSharedMemorySize, GEMM_SMEM);
    cudaFuncSetAttribute(attn_mma, cudaFuncAttributeMaxDynamicSharedMemorySize, ATTN_SMEM);

    // 1) fused prep: LoRA merges -> fp16 W; wk/wo -> fp16; x -> fp16 hi/lo
    prep_merge<<<2 * 65536, 256>>>(wq_w, wq_a, wq_b, wv_w, wv_a, wv_b, Wq, Wv);
    prep_split<<<3 * 8192, 256>>>(wk_w, wo_w, x, Wk, Wo, xh, xl);

    // 2) projections (fp16 2-term); RoPE fused (K), RoPE+scale fused (Q)
    dim3 g(D / 128, BSR / 128);
    gemm_f16x2<3><<<g, 256, GEMM_SMEM>>>(xh, xl, Wq, nullptr, Qh, Ql, fc, fs);
    gemm_f16x2<2><<<g, 256, GEMM_SMEM>>>(xh, xl, Wk, nullptr, Kh, Kl, fc, fs);
    gemm_f16x2<1><<<g, 256, GEMM_SMEM>>>(xh, xl, Wv, nullptr, Vh, Vl, fc, fs);

    // 3) MMA flash attention -> g_Oh/g_Ol (fp16 hi/lo)
    attn_mma<<<dim3(SEQ / 128, NH, 4), 256, ATTN_SMEM>>>();

    // 4) output projection (fp16 2-term, fp32 out)
    gemm_f16x2<0><<<g, 256, GEMM_SMEM>>>(Oh, Ol, Wo, out, nullptr, nullptr, fc, fs);
}

// round 12
// speedup vs baseline: 1.4581x; 1.0919x over previous
#include <cuda_runtime.h>
#include <cuda_bf16.h>
#include <cuda_fp16.h>
#include <cstdint>

#define D   4096
#define BSR 4096
#define SEQ 1024
#define NH  32
#define HD  128
#define LR  16
#define SCALE 0.08838834764831845f

// ------------------------- device scratch ---------------------------------
__device__ __half g_xh[(size_t)BSR * D], g_xl[(size_t)BSR * D];
__device__ __half g_Wq[(size_t)D * D], g_Wk[(size_t)D * D];
__device__ __half g_Wv[(size_t)D * D], g_Wo[(size_t)D * D];
__device__ __nv_bfloat16 g_Qh[(size_t)BSR * D], g_Ql[(size_t)BSR * D];
__device__ __nv_bfloat16 g_Kh[(size_t)BSR * D], g_Kl[(size_t)BSR * D];
__device__ __nv_bfloat16 g_Vh[(size_t)BSR * D], g_Vl[(size_t)BSR * D];
__device__ __half g_Oh[(size_t)BSR * D], g_Ol[(size_t)BSR * D];

// ------------------------- PTX helpers (base-target only) ------------------
__device__ __forceinline__ uint32_t smem_to_u32(const void* p) {
    uint32_t a;
    asm("{ .reg .u64 t; cvta.to.shared.u64 t, %1; cvt.u32.u64 %0, t; }"
        : "=r"(a) : "l"(p));
    return a;
}
#define CP16(dst, src) \
    asm volatile("cp.async.cg.shared.global [%0], [%1], 16;" \
                 :: "r"(dst), "l"(src))
#define CP_COMMIT() asm volatile("cp.async.commit_group;" ::: "memory")
#define CP_WAIT1()  asm volatile("cp.async.wait_group 1;" ::: "memory")
#define CP_WAIT0()  asm volatile("cp.async.wait_group 0;" ::: "memory")

#define LDSM4(r0, r1, r2, r3, addr) \
    asm volatile("ldmatrix.sync.aligned.m8n8.x4.shared.b16 {%0,%1,%2,%3}, [%4];" \
                 : "=r"(r0), "=r"(r1), "=r"(r2), "=r"(r3) : "r"(addr))
#define LDSM4T(r0, r1, r2, r3, addr) \
    asm volatile("ldmatrix.sync.aligned.m8n8.x4.trans.shared.b16 {%0,%1,%2,%3}, [%4];" \
                 : "=r"(r0), "=r"(r1), "=r"(r2), "=r"(r3) : "r"(addr))
#define LDSM2(r0, r1, addr) \
    asm volatile("ldmatrix.sync.aligned.m8n8.x2.shared.b16 {%0,%1}, [%2];" \
                 : "=r"(r0), "=r"(r1) : "r"(addr))
// bf16 mma (attention)
#define MMA16816(c, a0, a1, a2, a3, b0, b1) \
    asm volatile("mma.sync.aligned.m16n8k16.row.col.f32.bf16.bf16.f32 " \
                 "{%0,%1,%2,%3}, {%4,%5,%6,%7}, {%8,%9}, {%0,%1,%2,%3};" \
                 : "+f"((c)[0]), "+f"((c)[1]), "+f"((c)[2]), "+f"((c)[3]) \
                 : "r"(a0), "r"(a1), "r"(a2), "r"(a3), "r"(b0), "r"(b1))
// fp16 mma (projection GEMMs)
#define MMAF16(c, a0, a1, a2, a3, b0, b1) \
    asm volatile("mma.sync.aligned.m16n8k16.row.col.f32.f16.f16.f32 " \
                 "{%0,%1,%2,%3}, {%4,%5,%6,%7}, {%8,%9}, {%0,%1,%2,%3};" \
                 : "+f"((c)[0]), "+f"((c)[1]), "+f"((c)[2]), "+f"((c)[3]) \
                 : "r"(a0), "r"(a1), "r"(a2), "r"(a3), "r"(b0), "r"(b1))

// ------------------------- fused prep kernels ------------------------------
__global__ void prep_merge(const float* __restrict__ wq_w,
                           const float* __restrict__ wq_a,
                           const float* __restrict__ wq_b,
                           const float* __restrict__ wv_w,
                           const float* __restrict__ wv_a,
                           const float* __restrict__ wv_b,
                           __half* __restrict__ Wq,
                           __half* __restrict__ Wv) {
    const int sel = blockIdx.x >> 16;
    const int idx = ((blockIdx.x & 65535) << 8) + threadIdx.x;
    const float* w = sel ? wv_w : wq_w;
    const float* a = sel ? wv_a : wq_a;
    const float* b = sel ? wv_b : wq_b;
    __half* o      = sel ? Wv   : Wq;
    const int n = idx >> 12, k = idx & (D - 1);
    float acc = w[idx];
#pragma unroll
    for (int r = 0; r < LR; r++)
        acc += 2.0f * __ldg(&b[n * LR + r]) * __ldg(&a[r * D + k]);
    o[idx] = __float2half_rn(acc);
}

__global__ void prep_split(const float* __restrict__ wk_w,
                           const float* __restrict__ wo_w,
                           const float* __restrict__ x,
                           __half* __restrict__ Wk,
                           __half* __restrict__ Wo,
                           __half* __restrict__ xh,
                           __half* __restrict__ xl) {
    const int sel = blockIdx.x >> 13;
    const size_t i = (((size_t)(blockIdx.x & 8191) << 8) + threadIdx.x) * 8;
    const float* src = sel == 0 ? wk_w : (sel == 1 ? wo_w : x);
    float v[8];
    *(float4*)&v[0] = *(const float4*)(src + i);
    *(float4*)&v[4] = *(const float4*)(src + i + 4);
    __half h[8];
#pragma unroll
    for (int j = 0; j < 8; j++) h[j] = __float2half_rn(v[j]);
    if (sel == 2) {
        __half l[8];
#pragma unroll
        for (int j = 0; j < 8; j++)
            l[j] = __float2half_rn(v[j] - __half2float(h[j]));
        *(float4*)(xh + i) = *(float4*)h;
        *(float4*)(xl + i) = *(float4*)l;
    } else {
        __half* dst = sel == 0 ? Wk : Wo;
        *(float4*)(dst + i) = *(float4*)h;
    }
}

// ------------- fp16 2-term GEMM (NT), 2 CTAs/SM ----------------------------
// C = Ah*B^T + Al*B^T. BM=BN=128, BK=64, 256 thr (8 warps 2x4).
// 2 stages x 48KB = 96KB/CTA -> 2 CTAs/SM (192KB). Two barriers per chunk
// (issue-after-compute for the 2-stage ring). A-fragment registers reused
// across hi/lo passes to fit the 128-reg cap of __launch_bounds__(256,2).
// Per-accumulator MMA order (hi then lo per ks) identical to R11.
// MODE: 0 = fp32 store, 1 = bf16 split (V), 2 = RoPE+split (K),
//       3 = RoPE+scale+split (Q).
#define GTILE   16384
#define GSTAGE  (3 * GTILE)
#define GEMM_SMEM (2 * GSTAGE)
#define NCHUNK  64   // D / BK

template <int MODE>
__global__ void __launch_bounds__(256, 2) gemm_f16x2(
    const __half* __restrict__ Ah, const __half* __restrict__ Al,
    const __half* __restrict__ B,
    float* __restrict__ C,
    __nv_bfloat16* __restrict__ Ch, __nv_bfloat16* __restrict__ Cl,
    const float* __restrict__ fc, const float* __restrict__ fs) {
    extern __shared__ char smch[];
    const uint32_t smb = smem_to_u32(smch);
    const int tid = threadIdx.x, lane = tid & 31, wid = tid >> 5;
    const int warp_m = wid & 1;
    const int warp_n = wid >> 1;
    const int bm = blockIdx.y * 128, bn = blockIdx.x * 128;

    float acc[4][4][4];
#pragma unroll
    for (int i = 0; i < 4; i++)
#pragma unroll
        for (int j = 0; j < 4; j++)
#pragma unroll
            for (int k = 0; k < 4; k++) acc[i][j][k] = 0.0f;

    const int r0 = tid >> 3, c0 = tid & 7;
    const uint32_t dst0 = r0 * 128 + (uint32_t)((c0 ^ (r0 & 7)) * 16);
    const __half* gAh = Ah + ((size_t)(bm + r0) << 12) + c0 * 8;
    const __half* gAl = Al + ((size_t)(bm + r0) << 12) + c0 * 8;
    const __half* gB  = B  + ((size_t)(bn + r0) << 12) + c0 * 8;

#define ISSUE(ck, st) do {                                                     \
        const uint32_t sb_ = smb + (st) * GSTAGE + dst0;                       \
        const size_t go_ = (size_t)(ck) * 64;                                  \
        _Pragma("unroll")                                                      \
        for (int j = 0; j < 4; j++) {                                          \
            const uint32_t d_ = sb_ + j * 32 * 128;                            \
            const size_t s_ = go_ + ((size_t)j << 17);                         \
            CP16(d_,             (const char*)(gAh + s_));                     \
            CP16(d_ + GTILE,     (const char*)(gAl + s_));                     \
            CP16(d_ + 2 * GTILE, (const char*)(gB  + s_));                     \
        }                                                                      \
        CP_COMMIT();                                                           \
    } while (0)

    ISSUE(0, 0);
    ISSUE(1, 1);

    const int arow = warp_m * 64 + (lane & 15);
    const int akh  = lane >> 4;
    const int brow = warp_n * 32 + (lane & 7);
    const int bkh  = (lane >> 3) & 1;

    for (int ck = 0; ck < NCHUNK; ck++) {
        const int st = ck & 1;
        if (ck + 2 >= NCHUNK) { CP_WAIT0(); } else { CP_WAIT1(); }
        __syncthreads();

        const uint32_t sAh = smb + st * GSTAGE;
        const uint32_t sAl = sAh + GTILE;
        const uint32_t sB  = sAh + 2 * GTILE;

#pragma unroll
        for (int ks = 0; ks < 4; ks++) {
            uint32_t bb[4][2];
#pragma unroll
            for (int nt = 0; nt < 4; nt++) {
                const int r = brow + nt * 8;
                const uint32_t adr = r * 128 + (((ks * 2 + bkh) ^ (r & 7)) * 16);
                LDSM2(bb[nt][0], bb[nt][1], sB + adr);
            }
#pragma unroll
            for (int mt = 0; mt < 4; mt++) {
                const int r = arow + mt * 16;
                const uint32_t adr = r * 128 + (((ks * 2 + akh) ^ (r & 7)) * 16);
                uint32_t a0, a1, a2, a3;
                LDSM4(a0, a1, a2, a3, sAh + adr);     // hi fragments
#pragma unroll
                for (int nt = 0; nt < 4; nt++)
                    MMAF16(acc[mt][nt], a0, a1, a2, a3, bb[nt][0], bb[nt][1]);
                LDSM4(a0, a1, a2, a3, sAl + adr);     // lo fragments (reuse regs)
#pragma unroll
                for (int nt = 0; nt < 4; nt++)
                    MMAF16(acc[mt][nt], a0, a1, a2, a3, bb[nt][0], bb[nt][1]);
            }
        }
        __syncthreads();
        if (ck + 2 < NCHUNK) ISSUE(ck + 2, st);
    }

    // epilogue
#pragma unroll
    for (int mt = 0; mt < 4; mt++) {
        const int row = bm + warp_m * 64 + mt * 16 + (lane >> 2);
#pragma unroll
        for (int nt = 0; nt < 4; nt++) {
            const int col = bn + warp_n * 32 + nt * 8 + (lane & 3) * 2;
            float v0 = acc[mt][nt][0], v1 = acc[mt][nt][1];
            float v2 = acc[mt][nt][2], v3 = acc[mt][nt][3];
            if (MODE >= 2) {
                const int i = (col & (HD - 1)) >> 1;
                const int s1 = row & (SEQ - 1);
                const int s2 = (row + 8) & (SEQ - 1);
                const float c1 = __ldg(&fc[s1 * 64 + i]), n1 = __ldg(&fs[s1 * 64 + i]);
                const float c2 = __ldg(&fc[s2 * 64 + i]), n2 = __ldg(&fs[s2 * 64 + i]);
                float t;
                t  = v0 * c1 - v1 * n1; v1 = v0 * n1 + v1 * c1; v0 = t;
                t  = v2 * c2 - v3 * n2; v3 = v2 * n2 + v3 * c2; v2 = t;
            }
            if (MODE == 3) { v0 *= SCALE; v1 *= SCALE; v2 *= SCALE; v3 *= SCALE; }
            if (MODE == 0) {
                *(float2*)&C[(size_t)row * D + col]       = make_float2(v0, v1);
                *(float2*)&C[(size_t)(row + 8) * D + col] = make_float2(v2, v3);
            } else {
                __nv_bfloat16 h0 = __float2bfloat16(v0), h1 = __float2bfloat16(v1);
                __nv_bfloat162 hp; hp.x = h0; hp.y = h1;
                *(__nv_bfloat162*)&Ch[(size_t)row * D + col] = hp;
                __nv_bfloat162 lp;
                lp.x = __float2bfloat16(v0 - __bfloat162float(h0));
                lp.y = __float2bfloat16(v1 - __bfloat162float(h1));
                *(__nv_bfloat162*)&Cl[(size_t)row * D + col] = lp;
                __nv_bfloat16 h2 = __float2bfloat16(v2), h3 = __float2bfloat16(v3);
                __nv_bfloat162 hq; hq.x = h2; hq.y = h3;
                *(__nv_bfloat162*)&Ch[(size_t)(row + 8) * D + col] = hq;
                __nv_bfloat162 lq;
                lq.x = __float2bfloat16(v2 - __bfloat162float(h2));
                lq.y = __float2bfloat16(v3 - __bfloat162float(h3));
                *(__nv_bfloat162*)&Cl[(size_t)(row + 8) * D + col] = lq;
            }
        }
    }
}

// ---------------- MMA flash attention (bf16 hi/lo 3-term, causal) ----------
#define AT_Q    0
#define AT_QL   32768
#define AT_ST   65536
#define AT_STSZ 65536   // Kh | Kl | Vh | Vl (16KB each)
#define ATTN_SMEM (AT_ST + 2 * AT_STSZ)

__global__ void __launch_bounds__(256, 1) attn_mma() {
    extern __shared__ char smc[];
    const uint32_t smb = smem_to_u32(smc);
    const int b = blockIdx.z, h = blockIdx.y, qt = blockIdx.x;
    const int q0 = qt * 128;
    const int tid = threadIdx.x, lane = tid & 31, wid = tid >> 5;

    const size_t qoff = ((size_t)(b * SEQ + q0) << 12) + (size_t)h * HD;
    const size_t koff = ((size_t)(b * SEQ) << 12) + (size_t)h * HD;

#pragma unroll
    for (int j = 0; j < 8; j++) {
        int q = tid + 256 * j;
        int r = q >> 4, dt = q & 15;
        int srow = 2 * r + (dt >> 3);
        uint32_t adr = srow * 128 + (uint32_t)((((dt & 7)) ^ (srow & 7)) * 16);
        const size_t go = qoff + ((size_t)r << 12) + dt * 8;
        CP16(smb + AT_Q  + adr, (const char*)(g_Qh + go));
        CP16(smb + AT_QL + adr, (const char*)(g_Ql + go));
    }

#define ISSUE_KV(kt, st) do {                                                  \
        const size_t kb_ = koff + ((size_t)((kt) * 64) << 12);                 \
        const uint32_t sb_ = smb + AT_ST + (st) * AT_STSZ;                     \
        _Pragma("unroll")                                                      \
        for (int j = 0; j < 4; j++) {                                          \
            int q_ = tid + 256 * j;                                            \
            int r_ = q_ >> 4, dt_ = q_ & 15;                                   \
            int sr_ = 2 * r_ + (dt_ >> 3);                                     \
            uint32_t ad_ = sr_ * 128 + (uint32_t)(((dt_ & 7) ^ (sr_ & 7)) * 16); \
            const size_t g_ = kb_ + ((size_t)r_ << 12) + dt_ * 8;              \
            CP16(sb_ + ad_,         (const char*)(g_Kh + g_));                 \
            CP16(sb_ + 16384 + ad_, (const char*)(g_Kl + g_));                 \
            CP16(sb_ + 32768 + ad_, (const char*)(g_Vh + g_));                 \
            CP16(sb_ + 49152 + ad_, (const char*)(g_Vl + g_));                 \
        }                                                                      \
        CP_COMMIT();                                                           \
    } while (0)

    ISSUE_KV(0, 0);

    float o[16][4];
#pragma unroll
    for (int i = 0; i < 16; i++)
#pragma unroll
        for (int j = 0; j < 4; j++) o[i][j] = 0.0f;
    float m[2] = {-1e30f, -1e30f}, lsum[2] = {0.0f, 0.0f};

    const int ktiles = 2 * qt + 2;
    const int ar = wid * 16 + (lane & 15);
    const int akh = lane >> 4;

    for (int kt = 0; kt < ktiles; kt++) {
        const int st = kt & 1;
        if (kt + 1 < ktiles) { ISSUE_KV(kt + 1, st ^ 1); CP_WAIT1(); }
        else                 { CP_WAIT0(); }
        __syncthreads();

        const uint32_t sQh = smb + AT_Q, sQl = smb + AT_QL;
        const uint32_t sKh = smb + AT_ST + st * AT_STSZ;
        const uint32_t sKl = sKh + 16384, sVh = sKh + 32768, sVl = sKh + 49152;

        float sc[8][4];
#pragma unroll
        for (int t = 0; t < 8; t++)
#pragma unroll
            for (int j = 0; j < 4; j++) sc[t][j] = 0.0f;

#pragma unroll
        for (int ks = 0; ks < 8; ks++) {
            const int qs = 2 * ar + (ks >> 2);
            const uint32_t aadr = qs * 128 +
                (uint32_t)(((((ks & 3) * 2 + akh)) ^ (qs & 7)) * 16);
            uint32_t qh[4], ql[4];
            LDSM4(qh[0], qh[1], qh[2], qh[3], sQh + aadr);
            LDSM4(ql[0], ql[1], ql[2], ql[3], sQl + aadr);
            uint32_t kh4[4][4], kl4[4][4];
#pragma unroll
            for (int ntp = 0; ntp < 4; ntp++) {
                const int kr = ((lane >> 4) ? (2 * ntp + 1) : (2 * ntp)) * 8 + (lane & 7);
                const int kkh = (lane >> 3) & 1;
                const int ksr = 2 * kr + (ks >> 2);
                const uint32_t kadr = ksr * 128 +
                    (uint32_t)(((((ks & 3) * 2 + kkh)) ^ (ksr & 7)) * 16);
                LDSM4(kh4[ntp][0], kh4[ntp][1], kh4[ntp][2], kh4[ntp][3], sKh + kadr);
                LDSM4(kl4[ntp][0], kl4[ntp][1], kl4[ntp][2], kl4[ntp][3], sKl + kadr);
            }
#pragma unroll
            for (int ntp = 0; ntp < 4; ntp++) {
                MMA16816(sc[2*ntp],   qh[0], qh[1], qh[2], qh[3], kh4[ntp][0], kh4[ntp][1]);
                MMA16816(sc[2*ntp+1], qh[0], qh[1], qh[2], qh[3], kh4[ntp][2], kh4[ntp][3]);
            }
#pragma unroll
            for (int ntp = 0; ntp < 4; ntp++) {
                MMA16816(sc[2*ntp],   qh[0], qh[1], qh[2], qh[3], kl4[ntp][0], kl4[ntp][1]);
                MMA16816(sc[2*ntp+1], qh[0], qh[1], qh[2], qh[3], kl4[ntp][2], kl4[ntp][3]);
            }
#pragma unroll
            for (int ntp = 0; ntp < 4; ntp++) {
                MMA16816(sc[2*ntp],   ql[0], ql[1], ql[2], ql[3], kh4[ntp][0], kh4[ntp][1]);
                MMA16816(sc[2*ntp+1], ql[0], ql[1], ql[2], ql[3], kh4[ntp][2], kh4[ntp][3]);
            }
        }

        const int k0 = kt * 64;
        if (k0 + 63 > q0) {
            const int rb = q0 + wid * 16 + (lane >> 2);
#pragma unroll
            for (int t = 0; t < 8; t++) {
                const int cb = k0 + t * 8 + (lane & 3) * 2;
                if (cb     > rb)     sc[t][0] = -1e30f;
                if (cb + 1 > rb)     sc[t][1] = -1e30f;
                if (cb     > rb + 8) sc[t][2] = -1e30f;
                if (cb + 1 > rb + 8) sc[t][3] = -1e30f;
            }
        }

#pragma unroll
        for (int rh = 0; rh < 2; rh++) {
            float mx = -1e30f;
#pragma unroll
            for (int t = 0; t < 8; t++)
                mx = fmaxf(mx, fmaxf(sc[t][2*rh], sc[t][2*rh+1]));
            mx = fmaxf(mx, __shfl_xor_sync(0xffffffffu, mx, 1));
            mx = fmaxf(mx, __shfl_xor_sync(0xffffffffu, mx, 2));
            const float mnew = fmaxf(m[rh], mx);
            const float alpha = __expf(m[rh] - mnew);
            float s = 0.0f;
#pragma unroll
            for (int t = 0; t < 8; t++) {
                float p0 = __expf(sc[t][2*rh]   - mnew);
                float p1 = __expf(sc[t][2*rh+1] - mnew);
                sc[t][2*rh] = p0; sc[t][2*rh+1] = p1;
                s += p0 + p1;
            }
            s += __shfl_xor_sync(0xffffffffu, s, 1);
            s += __shfl_xor_sync(0xffffffffu, s, 2);
            lsum[rh] = lsum[rh] * alpha + s;
            m[rh] = mnew;
#pragma unroll
            for (int dt = 0; dt < 16; dt++) {
                o[dt][2*rh]   *= alpha;
                o[dt][2*rh+1] *= alpha;
            }
        }

#pragma unroll
        for (int kj = 0; kj < 4; kj++) {
            uint32_t ph[4], pl[4];
#pragma unroll
            for (int u = 0; u < 4; u++) {
                const float* sp = sc[2 * kj + (u >> 1)];
                const float v0 = sp[(u & 1) * 2], v1 = sp[(u & 1) * 2 + 1];
                __nv_bfloat16 h0 = __float2bfloat16(v0), h1 = __float2bfloat16(v1);
                __nv_bfloat162 hp; hp.x = h0; hp.y = h1;
                ph[u] = *(uint32_t*)&hp;
                __nv_bfloat162 lp;
                lp.x = __float2bfloat16(v0 - __bfloat162float(h0));
                lp.y = __float2bfloat16(v1 - __bfloat162float(h1));
                pl[u] = *(uint32_t*)&lp;
            }
            const int jr = kj * 16 + (lane & 7) + (((lane >> 3) & 1) << 3);
#pragma unroll
            for (int npp = 0; npp < 4; npp++) {
                const int np0 = 2 * npp, np1 = 2 * npp + 1;
                uint32_t vhA[4], vlA[4], vhB[4], vlB[4];
                {
                    const int dtc = 2 * np0 + (lane >> 4);
                    const int vsr = 2 * jr + (dtc >> 3);
                    const uint32_t vadr = vsr * 128 +
                        (uint32_t)((((dtc & 7)) ^ (vsr & 7)) * 16);
                    LDSM4T(vhA[0], vhA[1], vhA[2], vhA[3], sVh + vadr);
                    LDSM4T(vlA[0], vlA[1], vlA[2], vlA[3], sVl + vadr);
                }
                {
                    const int dtc = 2 * np1 + (lane >> 4);
                    const int vsr = 2 * jr + (dtc >> 3);
                    const uint32_t vadr = vsr * 128 +
                        (uint32_t)((((dtc & 7)) ^ (vsr & 7)) * 16);
                    LDSM4T(vhB[0], vhB[1], vhB[2], vhB[3], sVh + vadr);
                    LDSM4T(vlB[0], vlB[1], vlB[2], vlB[3], sVl + vadr);
                }
                MMA16816(o[2*np0],   ph[0], ph[1], ph[2], ph[3], vhA[0], vhA[1]);
                MMA16816(o[2*np0+1], ph[0], ph[1], ph[2], ph[3], vhA[2], vhA[3]);
                MMA16816(o[2*np1],   ph[0], ph[1], ph[2], ph[3], vhB[0], vhB[1]);
                MMA16816(o[2*np1+1], ph[0], ph[1], ph[2], ph[3], vhB[2], vhB[3]);
                MMA16816(o[2*np0],   ph[0], ph[1], ph[2], ph[3], vlA[0], vlA[1]);
                MMA16816(o[2*np0+1], ph[0], ph[1], ph[2], ph[3], vlA[2], vlA[3]);
                MMA16816(o[2*np1],   ph[0], ph[1], ph[2], ph[3], vlB[0], vlB[1]);
                MMA16816(o[2*np1+1], ph[0], ph[1], ph[2], ph[3], vlB[2], vlB[3]);
                MMA16816(o[2*np0],   pl[0], pl[1], pl[2], pl[3], vhA[0], vhA[1]);
                MMA16816(o[2*np0+1], pl[0], pl[1], pl[2], pl[3], vhA[2], vhA[3]);
                MMA16816(o[2*np1],   pl[0], pl[1], pl[2], pl[3], vhB[0], vhB[1]);
                MMA16816(o[2*np1+1], pl[0], pl[1], pl[2], pl[3], vhB[2], vhB[3]);
            }
        }
        __syncthreads();
    }

    // ---- epilogue: normalize + fp16 hi/lo split (feeds fp16 O-GEMM) ----
#pragma unroll
    for (int rh = 0; rh < 2; rh++) {
        const float inv = 1.0f / lsum[rh];
        const int row = q0 + wid * 16 + (lane >> 2) + rh * 8;
        const size_t ro = ((size_t)(b * SEQ + row) << 12) + (size_t)h * HD
                          + (lane & 3) * 2;
#pragma unroll
        for (int dt = 0; dt < 16; dt++) {
            const float v0 = o[dt][2*rh] * inv, v1 = o[dt][2*rh+1] * inv;
            __half h0 = __float2half_rn(v0), h1 = __float2half_rn(v1);
            __half2 hp; hp.x = h0; hp.y = h1;
            *(__half2*)&g_Oh[ro + dt * 8] = hp;
            __half2 lp;
            lp.x = __float2half_rn(v0 - __half2float(h0));
            lp.y = __float2half_rn(v1 - __half2float(h1));
            *(__half2*)&g_Ol[ro + dt * 8] = lp;
        }
    }
}

// ---------------- launcher -------------------------------------------------
extern "C" void kernel_launch(void* const* d_in, const int* in_sizes, int n_in,
                              void* d_out, int out_size) {
    const float* x    = (const float*)d_in[0];
    const float* wq_w = (const float*)d_in[1];
    const float* wq_a = (const float*)d_in[2];
    const float* wq_b = (const float*)d_in[3];
    const float* wk_w = (const float*)d_in[4];
    const float* wv_w = (const float*)d_in[5];
    const float* wv_a = (const float*)d_in[6];
    const float* wv_b = (const float*)d_in[7];
    const float* wo_w = (const float*)d_in[8];
    const float* fc   = (const float*)d_in[9];
    const float* fs   = (const float*)d_in[10];
    float* out = (float*)d_out;

    __half *xh, *xl, *Wq, *Wk, *Wv, *Wo, *Oh, *Ol;
    __nv_bfloat16 *Qh, *Ql, *Kh, *Kl, *Vh, *Vl;
    cudaGetSymbolAddress((void**)&xh, g_xh); cudaGetSymbolAddress((void**)&xl, g_xl);
    cudaGetSymbolAddress((void**)&Wq, g_Wq); cudaGetSymbolAddress((void**)&Wk, g_Wk);
    cudaGetSymbolAddress((void**)&Wv, g_Wv); cudaGetSymbolAddress((void**)&Wo, g_Wo);
    cudaGetSymbolAddress((void**)&Qh, g_Qh); cudaGetSymbolAddress((void**)&Ql, g_Ql);
    cudaGetSymbolAddress((void**)&Kh, g_Kh); cudaGetSymbolAddress((void**)&Kl, g_Kl);
    cudaGetSymbolAddress((void**)&Vh, g_Vh); cudaGetSymbolAddress((void**)&Vl, g_Vl);
    cudaGetSymbolAddress((void**)&Oh, g_Oh); cudaGetSymbolAddress((void**)&Ol, g_Ol);

    cudaFuncSetAttribute(gemm_f16x2<0>, cudaFuncAttributeMaxDynamicSharedMemorySize, GEMM_SMEM);
    cudaFuncSetAttribute(gemm_f16x2<1>, cudaFuncAttributeMaxDynamicSharedMemorySize, GEMM_SMEM);
    cudaFuncSetAttribute(gemm_f16x2<2>, cudaFuncAttributeMaxDynamicSharedMemorySize, GEMM_SMEM);
    cudaFuncSetAttribute(gemm_f16x2<3>, cudaFuncAttributeMaxDynamicSharedMemorySize, GEMM_SMEM);
    cudaFuncSetAttribute(attn_mma, cudaFuncAttributeMaxDynamicSharedMemorySize, ATTN_SMEM);

    // 1) fused prep
    prep_merge<<<2 * 65536, 256>>>(wq_w, wq_a, wq_b, wv_w, wv_a, wv_b, Wq, Wv);
    prep_split<<<3 * 8192, 256>>>(wk_w, wo_w, x, Wk, Wo, xh, xl);

    // 2) projections (fp16 2-term, 2 CTAs/SM); RoPE fused (K), RoPE+scale (Q)
    dim3 g(D / 128, BSR / 128);
    gemm_f16x2<3><<<g, 256, GEMM_SMEM>>>(xh, xl, Wq, nullptr, Qh, Ql, fc, fs);
    gemm_f16x2<2><<<g, 256, GEMM_SMEM>>>(xh, xl, Wk, nullptr, Kh, Kl, fc, fs);
    gemm_f16x2<1><<<g, 256, GEMM_SMEM>>>(xh, xl, Wv, nullptr, Vh, Vl, fc, fs);

    // 3) MMA flash attention -> g_Oh/g_Ol (fp16 hi/lo)
    attn_mma<<<dim3(SEQ / 128, NH, 4), 256, ATTN_SMEM>>>();

    // 4) output projection (fp16 2-term, fp32 out)
    gemm_f16x2<0><<<g, 256, GEMM_SMEM>>>(Oh, Ol, Wo, out, nullptr, nullptr, fc, fs);
}

// round 13
// speedup vs baseline: 1.5961x; 1.0946x over previous
#include <cuda_runtime.h>
#include <cuda_bf16.h>
#include <cuda_fp16.h>
#include <cstdint>

#define D   4096
#define BSR 4096
#define SEQ 1024
#define NH  32
#define HD  128
#define LR  16
#define SCALE 0.08838834764831845f

// ------------------------- device scratch ---------------------------------
__device__ __half g_xh[(size_t)BSR * D], g_xl[(size_t)BSR * D];
__device__ __half g_Wq[(size_t)D * D], g_Wk[(size_t)D * D];
__device__ __half g_Wv[(size_t)D * D], g_Wo[(size_t)D * D];
__device__ __half g_Q[(size_t)BSR * D], g_K[(size_t)BSR * D], g_V[(size_t)BSR * D];
__device__ __half g_Oh[(size_t)BSR * D], g_Ol[(size_t)BSR * D];

// ------------------------- PTX helpers (base-target only) ------------------
__device__ __forceinline__ uint32_t smem_to_u32(const void* p) {
    uint32_t a;
    asm("{ .reg .u64 t; cvta.to.shared.u64 t, %1; cvt.u32.u64 %0, t; }"
        : "=r"(a) : "l"(p));
    return a;
}
#define CP16(dst, src) \
    asm volatile("cp.async.cg.shared.global [%0], [%1], 16;" \
                 :: "r"(dst), "l"(src))
#define CP_COMMIT() asm volatile("cp.async.commit_group;" ::: "memory")
#define CP_WAIT1()  asm volatile("cp.async.wait_group 1;" ::: "memory")
#define CP_WAIT0()  asm volatile("cp.async.wait_group 0;" ::: "memory")

#define LDSM4(r0, r1, r2, r3, addr) \
    asm volatile("ldmatrix.sync.aligned.m8n8.x4.shared.b16 {%0,%1,%2,%3}, [%4];" \
                 : "=r"(r0), "=r"(r1), "=r"(r2), "=r"(r3) : "r"(addr))
#define LDSM4T(r0, r1, r2, r3, addr) \
    asm volatile("ldmatrix.sync.aligned.m8n8.x4.trans.shared.b16 {%0,%1,%2,%3}, [%4];" \
                 : "=r"(r0), "=r"(r1), "=r"(r2), "=r"(r3) : "r"(addr))
#define LDSM2(r0, r1, addr) \
    asm volatile("ldmatrix.sync.aligned.m8n8.x2.shared.b16 {%0,%1}, [%2];" \
                 : "=r"(r0), "=r"(r1) : "r"(addr))
#define MMAF16(c, a0, a1, a2, a3, b0, b1) \
    asm volatile("mma.sync.aligned.m16n8k16.row.col.f32.f16.f16.f32 " \
                 "{%0,%1,%2,%3}, {%4,%5,%6,%7}, {%8,%9}, {%0,%1,%2,%3};" \
                 : "+f"((c)[0]), "+f"((c)[1]), "+f"((c)[2]), "+f"((c)[3]) \
                 : "r"(a0), "r"(a1), "r"(a2), "r"(a3), "r"(b0), "r"(b1))

// ------------------------- fused prep kernels ------------------------------
__global__ void prep_merge(const float* __restrict__ wq_w,
                           const float* __restrict__ wq_a,
                           const float* __restrict__ wq_b,
                           const float* __restrict__ wv_w,
                           const float* __restrict__ wv_a,
                           const float* __restrict__ wv_b,
                           __half* __restrict__ Wq,
                           __half* __restrict__ Wv) {
    const int sel = blockIdx.x >> 16;
    const int idx = ((blockIdx.x & 65535) << 8) + threadIdx.x;
    const float* w = sel ? wv_w : wq_w;
    const float* a = sel ? wv_a : wq_a;
    const float* b = sel ? wv_b : wq_b;
    __half* o      = sel ? Wv   : Wq;
    const int n = idx >> 12, k = idx & (D - 1);
    float acc = w[idx];
#pragma unroll
    for (int r = 0; r < LR; r++)
        acc += 2.0f * __ldg(&b[n * LR + r]) * __ldg(&a[r * D + k]);
    o[idx] = __float2half_rn(acc);
}

__global__ void prep_split(const float* __restrict__ wk_w,
                           const float* __restrict__ wo_w,
                           const float* __restrict__ x,
                           __half* __restrict__ Wk,
                           __half* __restrict__ Wo,
                           __half* __restrict__ xh,
                           __half* __restrict__ xl) {
    const int sel = blockIdx.x >> 13;
    const size_t i = (((size_t)(blockIdx.x & 8191) << 8) + threadIdx.x) * 8;
    const float* src = sel == 0 ? wk_w : (sel == 1 ? wo_w : x);
    float v[8];
    *(float4*)&v[0] = *(const float4*)(src + i);
    *(float4*)&v[4] = *(const float4*)(src + i + 4);
    __half h[8];
#pragma unroll
    for (int j = 0; j < 8; j++) h[j] = __float2half_rn(v[j]);
    if (sel == 2) {
        __half l[8];
#pragma unroll
        for (int j = 0; j < 8; j++)
            l[j] = __float2half_rn(v[j] - __half2float(h[j]));
        *(float4*)(xh + i) = *(float4*)h;
        *(float4*)(xl + i) = *(float4*)l;
    } else {
        __half* dst = sel == 0 ? Wk : Wo;
        *(float4*)(dst + i) = *(float4*)h;
    }
}

// ------------- fp16 2-term GEMM (NT), 2 CTAs/SM ----------------------------
// C = Ah*B^T + Al*B^T. BM=BN=128, BK=64, 256 thr. 2 stages, 96KB/CTA.
// MODE 0: single output (fp32 C) — O projection.  Grid (32, 32, 1).
// MODE 1: fused QKV — blockIdx.z selects B/out/epilogue:
//         z=0: Q = RoPE+scale -> fp16; z=1: K = RoPE -> fp16; z=2: V -> fp16.
#define GTILE   16384
#define GSTAGE  (3 * GTILE)
#define GEMM_SMEM (2 * GSTAGE)
#define NCHUNK  64   // D / BK

template <int MODE>
__global__ void __launch_bounds__(256, 2) gemm16(
    const __half* __restrict__ Ah, const __half* __restrict__ Al,
    const __half* __restrict__ B0, const __half* __restrict__ B1,
    const __half* __restrict__ B2,
    float* __restrict__ C,
    __half* __restrict__ O0, __half* __restrict__ O1, __half* __restrict__ O2,
    const float* __restrict__ fc, const float* __restrict__ fs) {
    extern __shared__ char smch[];
    const uint32_t smb = smem_to_u32(smch);
    const int tid = threadIdx.x, lane = tid & 31, wid = tid >> 5;
    const int warp_m = wid & 1;
    const int warp_n = wid >> 1;
    const int bm = blockIdx.y * 128, bn = blockIdx.x * 128;
    const int z = blockIdx.z;
    const __half* B = (MODE == 0) ? B0 : (z == 0 ? B0 : (z == 1 ? B1 : B2));

    float acc[4][4][4];
#pragma unroll
    for (int i = 0; i < 4; i++)
#pragma unroll
        for (int j = 0; j < 4; j++)
#pragma unroll
            for (int k = 0; k < 4; k++) acc[i][j][k] = 0.0f;

    const int r0 = tid >> 3, c0 = tid & 7;
    const uint32_t dst0 = r0 * 128 + (uint32_t)((c0 ^ (r0 & 7)) * 16);
    const __half* gAh = Ah + ((size_t)(bm + r0) << 12) + c0 * 8;
    const __half* gAl = Al + ((size_t)(bm + r0) << 12) + c0 * 8;
    const __half* gB  = B  + ((size_t)(bn + r0) << 12) + c0 * 8;

#define ISSUE(ck, st) do {                                                     \
        const uint32_t sb_ = smb + (st) * GSTAGE + dst0;                       \
        const size_t go_ = (size_t)(ck) * 64;                                  \
        _Pragma("unroll")                                                      \
        for (int j = 0; j < 4; j++) {                                          \
            const uint32_t d_ = sb_ + j * 32 * 128;                            \
            const size_t s_ = go_ + ((size_t)j << 17);                         \
            CP16(d_,             (const char*)(gAh + s_));                     \
            CP16(d_ + GTILE,     (const char*)(gAl + s_));                     \
            CP16(d_ + 2 * GTILE, (const char*)(gB  + s_));                     \
        }                                                                      \
        CP_COMMIT();                                                           \
    } while (0)

    ISSUE(0, 0);
    ISSUE(1, 1);

    const int arow = warp_m * 64 + (lane & 15);
    const int akh  = lane >> 4;
    const int brow = warp_n * 32 + (lane & 7);
    const int bkh  = (lane >> 3) & 1;

    for (int ck = 0; ck < NCHUNK; ck++) {
        const int st = ck & 1;
        if (ck + 2 >= NCHUNK) { CP_WAIT0(); } else { CP_WAIT1(); }
        __syncthreads();

        const uint32_t sAh = smb + st * GSTAGE;
        const uint32_t sAl = sAh + GTILE;
        const uint32_t sB  = sAh + 2 * GTILE;

#pragma unroll
        for (int ks = 0; ks < 4; ks++) {
            uint32_t bb[4][2];
#pragma unroll
            for (int nt = 0; nt < 4; nt++) {
                const int r = brow + nt * 8;
                const uint32_t adr = r * 128 + (((ks * 2 + bkh) ^ (r & 7)) * 16);
                LDSM2(bb[nt][0], bb[nt][1], sB + adr);
            }
#pragma unroll
            for (int mt = 0; mt < 4; mt++) {
                const int r = arow + mt * 16;
                const uint32_t adr = r * 128 + (((ks * 2 + akh) ^ (r & 7)) * 16);
                uint32_t a0, a1, a2, a3;
                LDSM4(a0, a1, a2, a3, sAh + adr);
#pragma unroll
                for (int nt = 0; nt < 4; nt++)
                    MMAF16(acc[mt][nt], a0, a1, a2, a3, bb[nt][0], bb[nt][1]);
                LDSM4(a0, a1, a2, a3, sAl + adr);
#pragma unroll
                for (int nt = 0; nt < 4; nt++)
                    MMAF16(acc[mt][nt], a0, a1, a2, a3, bb[nt][0], bb[nt][1]);
            }
        }
        __syncthreads();
        if (ck + 2 < NCHUNK) ISSUE(ck + 2, st);
    }

    // epilogue
    __half* outp = (MODE == 1) ? (z == 0 ? O0 : (z == 1 ? O1 : O2)) : (__half*)0;
    const bool doRope  = (MODE == 1) && (z < 2);
    const bool doScale = (MODE == 1) && (z == 0);
#pragma unroll
    for (int mt = 0; mt < 4; mt++) {
        const int row = bm + warp_m * 64 + mt * 16 + (lane >> 2);
#pragma unroll
        for (int nt = 0; nt < 4; nt++) {
            const int col = bn + warp_n * 32 + nt * 8 + (lane & 3) * 2;
            float v0 = acc[mt][nt][0], v1 = acc[mt][nt][1];
            float v2 = acc[mt][nt][2], v3 = acc[mt][nt][3];
            if (doRope) {
                const int i = (col & (HD - 1)) >> 1;
                const int s1 = row & (SEQ - 1);
                const int s2 = (row + 8) & (SEQ - 1);
                const float c1 = __ldg(&fc[s1 * 64 + i]), n1 = __ldg(&fs[s1 * 64 + i]);
                const float c2 = __ldg(&fc[s2 * 64 + i]), n2 = __ldg(&fs[s2 * 64 + i]);
                float t;
                t  = v0 * c1 - v1 * n1; v1 = v0 * n1 + v1 * c1; v0 = t;
                t  = v2 * c2 - v3 * n2; v3 = v2 * n2 + v3 * c2; v2 = t;
            }
            if (doScale) { v0 *= SCALE; v1 *= SCALE; v2 *= SCALE; v3 *= SCALE; }
            if (MODE == 0) {
                *(float2*)&C[(size_t)row * D + col]       = make_float2(v0, v1);
                *(float2*)&C[(size_t)(row + 8) * D + col] = make_float2(v2, v3);
            } else {
                __half2 p; p.x = __float2half_rn(v0); p.y = __float2half_rn(v1);
                *(__half2*)&outp[(size_t)row * D + col] = p;
                __half2 q; q.x = __float2half_rn(v2); q.y = __float2half_rn(v3);
                *(__half2*)&outp[(size_t)(row + 8) * D + col] = q;
            }
        }
    }
}

// ---------------- MMA flash attention (fp16 1-term, causal) ----------------
// Q pre-scaled by 1/sqrt(HD). Q tile 128x128 fp16 (32KB, loaded once);
// K/V tiles 64x128 fp16, double-buffered (32KB/stage). FA2 register softmax;
// P fp16 fragments built in-register; PV via ldmatrix.trans.
// O written as fp16 hi/lo (exact split) for the 2-term O-GEMM.
#define AT_Q    0
#define AT_ST   32768
#define AT_STSZ 32768   // K 16KB | V 16KB
#define ATTN_SMEM (AT_ST + 2 * AT_STSZ)

__global__ void __launch_bounds__(256, 1) attn_mma() {
    extern __shared__ char smc[];
    const uint32_t smb = smem_to_u32(smc);
    const int b = blockIdx.z, h = blockIdx.y, qt = blockIdx.x;
    const int q0 = qt * 128;
    const int tid = threadIdx.x, lane = tid & 31, wid = tid >> 5;

    const size_t qoff = ((size_t)(b * SEQ + q0) << 12) + (size_t)h * HD;
    const size_t koff = ((size_t)(b * SEQ) << 12) + (size_t)h * HD;

    // Q load: 2048 16B-chunks, 8 per thread
#pragma unroll
    for (int j = 0; j < 8; j++) {
        int q = tid + 256 * j;
        int r = q >> 4, dt = q & 15;
        int srow = 2 * r + (dt >> 3);
        uint32_t adr = srow * 128 + (uint32_t)((((dt & 7)) ^ (srow & 7)) * 16);
        CP16(smb + AT_Q + adr, (const char*)(g_Q + qoff + ((size_t)r << 12) + dt * 8));
    }

#define ISSUE_KV(kt, st) do {                                                  \
        const size_t kb_ = koff + ((size_t)((kt) * 64) << 12);                 \
        const uint32_t sb_ = smb + AT_ST + (st) * AT_STSZ;                     \
        _Pragma("unroll")                                                      \
        for (int j = 0; j < 4; j++) {                                          \
            int q_ = tid + 256 * j;                                            \
            int r_ = q_ >> 4, dt_ = q_ & 15;                                   \
            int sr_ = 2 * r_ + (dt_ >> 3);                                     \
            uint32_t ad_ = sr_ * 128 + (uint32_t)(((dt_ & 7) ^ (sr_ & 7)) * 16); \
            const size_t g_ = kb_ + ((size_t)r_ << 12) + dt_ * 8;              \
            CP16(sb_ + ad_,         (const char*)(g_K + g_));                  \
            CP16(sb_ + 16384 + ad_, (const char*)(g_V + g_));                  \
        }                                                                      \
        CP_COMMIT();                                                           \
    } while (0)

    ISSUE_KV(0, 0);

    float o[16][4];
#pragma unroll
    for (int i = 0; i < 16; i++)
#pragma unroll
        for (int j = 0; j < 4; j++) o[i][j] = 0.0f;
    float m[2] = {-1e30f, -1e30f}, lsum[2] = {0.0f, 0.0f};

    const int ktiles = 2 * qt + 2;
    const int ar = wid * 16 + (lane & 15);
    const int akh = lane >> 4;

    for (int kt = 0; kt < ktiles; kt++) {
        const int st = kt & 1;
        if (kt + 1 < ktiles) { ISSUE_KV(kt + 1, st ^ 1); CP_WAIT1(); }
        else                 { CP_WAIT0(); }
        __syncthreads();

        const uint32_t sQ = smb + AT_Q;
        const uint32_t sK = smb + AT_ST + st * AT_STSZ;
        const uint32_t sV = sK + 16384;

        // ---- S = Q K^T (1-term fp16) ----
        float sc[8][4];
#pragma unroll
        for (int t = 0; t < 8; t++)
#pragma unroll
            for (int j = 0; j < 4; j++) sc[t][j] = 0.0f;

#pragma unroll
        for (int ks = 0; ks < 8; ks++) {
            const int qs = 2 * ar + (ks >> 2);
            const uint32_t aadr = qs * 128 +
                (uint32_t)(((((ks & 3) * 2 + akh)) ^ (qs & 7)) * 16);
            uint32_t qf[4];
            LDSM4(qf[0], qf[1], qf[2], qf[3], sQ + aadr);
#pragma unroll
            for (int ntp = 0; ntp < 4; ntp++) {
                const int kr = ((lane >> 4) ? (2 * ntp + 1) : (2 * ntp)) * 8 + (lane & 7);
                const int kkh = (lane >> 3) & 1;
                const int ksr = 2 * kr + (ks >> 2);
                const uint32_t kadr = ksr * 128 +
                    (uint32_t)(((((ks & 3) * 2 + kkh)) ^ (ksr & 7)) * 16);
                uint32_t kf[4];
                LDSM4(kf[0], kf[1], kf[2], kf[3], sK + kadr);
                MMAF16(sc[2*ntp],   qf[0], qf[1], qf[2], qf[3], kf[0], kf[1]);
                MMAF16(sc[2*ntp+1], qf[0], qf[1], qf[2], qf[3], kf[2], kf[3]);
            }
        }

        // ---- causal mask ----
        const int k0 = kt * 64;
        if (k0 + 63 > q0) {
            const int rb = q0 + wid * 16 + (lane >> 2);
#pragma unroll
            for (int t = 0; t < 8; t++) {
                const int cb = k0 + t * 8 + (lane & 3) * 2;
                if (cb     > rb)     sc[t][0] = -1e30f;
                if (cb + 1 > rb)     sc[t][1] = -1e30f;
                if (cb     > rb + 8) sc[t][2] = -1e30f;
                if (cb + 1 > rb + 8) sc[t][3] = -1e30f;
            }
        }

        // ---- online softmax ----
#pragma unroll
        for (int rh = 0; rh < 2; rh++) {
            float mx = -1e30f;
#pragma unroll
            for (int t = 0; t < 8; t++)
                mx = fmaxf(mx, fmaxf(sc[t][2*rh], sc[t][2*rh+1]));
            mx = fmaxf(mx, __shfl_xor_sync(0xffffffffu, mx, 1));
            mx = fmaxf(mx, __shfl_xor_sync(0xffffffffu, mx, 2));
            const float mnew = fmaxf(m[rh], mx);
            const float alpha = __expf(m[rh] - mnew);
            float s = 0.0f;
#pragma unroll
            for (int t = 0; t < 8; t++) {
                float p0 = __expf(sc[t][2*rh]   - mnew);
                float p1 = __expf(sc[t][2*rh+1] - mnew);
                sc[t][2*rh] = p0; sc[t][2*rh+1] = p1;
                s += p0 + p1;
            }
            s += __shfl_xor_sync(0xffffffffu, s, 1);
            s += __shfl_xor_sync(0xffffffffu, s, 2);
            lsum[rh] = lsum[rh] * alpha + s;
            m[rh] = mnew;
#pragma unroll
            for (int dt = 0; dt < 16; dt++) {
                o[dt][2*rh]   *= alpha;
                o[dt][2*rh+1] *= alpha;
            }
        }

        // ---- O += P V (1-term fp16) ----
#pragma unroll
        for (int kj = 0; kj < 4; kj++) {
            uint32_t ph[4];
#pragma unroll
            for (int u = 0; u < 4; u++) {
                const float* sp = sc[2 * kj + (u >> 1)];
                __half2 hp;
                hp.x = __float2half_rn(sp[(u & 1) * 2]);
                hp.y = __float2half_rn(sp[(u & 1) * 2 + 1]);
                ph[u] = *(uint32_t*)&hp;
            }
            const int jr = kj * 16 + (lane & 7) + (((lane >> 3) & 1) << 3);
#pragma unroll
            for (int npp = 0; npp < 4; npp++) {
                const int np0 = 2 * npp, np1 = 2 * npp + 1;
                uint32_t vA[4], vB[4];
                {
                    const int dtc = 2 * np0 + (lane >> 4);
                    const int vsr = 2 * jr + (dtc >> 3);
                    const uint32_t vadr = vsr * 128 +
                        (uint32_t)((((dtc & 7)) ^ (vsr & 7)) * 16);
                    LDSM4T(vA[0], vA[1], vA[2], vA[3], sV + vadr);
                }
                {
                    const int dtc = 2 * np1 + (lane >> 4);
                    const int vsr = 2 * jr + (dtc >> 3);
                    const uint32_t vadr = vsr * 128 +
                        (uint32_t)((((dtc & 7)) ^ (vsr & 7)) * 16);
                    LDSM4T(vB[0], vB[1], vB[2], vB[3], sV + vadr);
                }
                MMAF16(o[2*np0],   ph[0], ph[1], ph[2], ph[3], vA[0], vA[1]);
                MMAF16(o[2*np0+1], ph[0], ph[1], ph[2], ph[3], vA[2], vA[3]);
                MMAF16(o[2*np1],   ph[0], ph[1], ph[2], ph[3], vB[0], vB[1]);
                MMAF16(o[2*np1+1], ph[0], ph[1], ph[2], ph[3], vB[2], vB[3]);
            }
        }
        __syncthreads();
    }

    // ---- epilogue: normalize + fp16 hi/lo split (feeds 2-term O-GEMM) ----
#pragma unroll
    for (int rh = 0; rh < 2; rh++) {
        const float inv = 1.0f / lsum[rh];
        const int row = q0 + wid * 16 + (lane >> 2) + rh * 8;
        const size_t ro = ((size_t)(b * SEQ + row) << 12) + (size_t)h * HD
                          + (lane & 3) * 2;
#pragma unroll
        for (int dt = 0; dt < 16; dt++) {
            const float v0 = o[dt][2*rh] * inv, v1 = o[dt][2*rh+1] * inv;
            __half h0 = __float2half_rn(v0), h1 = __float2half_rn(v1);
            __half2 hp; hp.x = h0; hp.y = h1;
            *(__half2*)&g_Oh[ro + dt * 8] = hp;
            __half2 lp;
            lp.x = __float2half_rn(v0 - __half2float(h0));
            lp.y = __float2half_rn(v1 - __half2float(h1));
            *(__half2*)&g_Ol[ro + dt * 8] = lp;
        }
    }
}

// ---------------- launcher -------------------------------------------------
extern "C" void kernel_launch(void* const* d_in, const int* in_sizes, int n_in,
                              void* d_out, int out_size) {
    const float* x    = (const float*)d_in[0];
    const float* wq_w = (const float*)d_in[1];
    const float* wq_a = (const float*)d_in[2];
    const float* wq_b = (const float*)d_in[3];
    const float* wk_w = (const float*)d_in[4];
    const float* wv_w = (const float*)d_in[5];
    const float* wv_a = (const float*)d_in[6];
    const float* wv_b = (const float*)d_in[7];
    const float* wo_w = (const float*)d_in[8];
    const float* fc   = (const float*)d_in[9];
    const float* fs   = (const float*)d_in[10];
    float* out = (float*)d_out;

    __half *xh, *xl, *Wq, *Wk, *Wv, *Wo, *Q, *K, *V, *Oh, *Ol;
    cudaGetSymbolAddress((void**)&xh, g_xh); cudaGetSymbolAddress((void**)&xl, g_xl);
    cudaGetSymbolAddress((void**)&Wq, g_Wq); cudaGetSymbolAddress((void**)&Wk, g_Wk);
    cudaGetSymbolAddress((void**)&Wv, g_Wv); cudaGetSymbolAddress((void**)&Wo, g_Wo);
    cudaGetSymbolAddress((void**)&Q, g_Q);   cudaGetSymbolAddress((void**)&K, g_K);
    cudaGetSymbolAddress((void**)&V, g_V);
    cudaGetSymbolAddress((void**)&Oh, g_Oh); cudaGetSymbolAddress((void**)&Ol, g_Ol);

    cudaFuncSetAttribute(gemm16<0>, cudaFuncAttributeMaxDynamicSharedMemorySize, GEMM_SMEM);
    cudaFuncSetAttribute(gemm16<1>, cudaFuncAttributeMaxDynamicSharedMemorySize, GEMM_SMEM);
    cudaFuncSetAttribute(attn_mma, cudaFuncAttributeMaxDynamicSharedMemorySize, ATTN_SMEM);

    // 1) fused prep
    prep_merge<<<2 * 65536, 256>>>(wq_w, wq_a, wq_b, wv_w, wv_a, wv_b, Wq, Wv);
    prep_split<<<3 * 8192, 256>>>(wk_w, wo_w, x, Wk, Wo, xh, xl);

    // 2) fused QKV projection (one launch, 3072 tiles)
    gemm16<1><<<dim3(D / 128, BSR / 128, 3), 256, GEMM_SMEM>>>(
        xh, xl, Wq, Wk, Wv, nullptr, Q, K, V, fc, fs);

    // 3) fp16 1-term MMA flash attention -> g_Oh/g_Ol (exact fp16 split)
    attn_mma<<<dim3(SEQ / 128, NH, 4), 256, ATTN_SMEM>>>();

    // 4) output projection (fp16 2-term, fp32 out)
    gemm16<0><<<dim3(D / 128, BSR / 128, 1), 256, GEMM_SMEM>>>(
        Oh, Ol, Wo, nullptr, nullptr, out, nullptr, nullptr, nullptr, fc, fs);
}